// round 2
// baseline (speedup 1.0000x reference)
#include <cuda_runtime.h>
#include <cstdint>
#include <math.h>

#define D_MODEL 1024
#define NHEAD   16
#define HD      64
#define SEQ     2048
#define BATCH   4
#define MTOT    (BATCH*SEQ)      // 8192
#define BHN     (BATCH*NHEAD)    // 64

// scratch (static __device__ arrays are the allowed scratch mechanism)
static __device__ float g_xln[MTOT * D_MODEL];
static __device__ float g_q[BHN * SEQ * HD];
static __device__ float g_k[BHN * SEQ * HD];
static __device__ float g_v[BHN * SEQ * HD];
static __device__ float g_ctx[MTOT * D_MODEL];
static __device__ float g_emb[SEQ * HD];

// ---------------------------------------------------------------------------
// rotary table: emb[s, d] = d<32 ? sin(s*invf[d]) : cos(s*invf[d-32])
// ---------------------------------------------------------------------------
__global__ void emb_kernel() {
    int idx = blockIdx.x * blockDim.x + threadIdx.x;
    if (idx >= SEQ * HD) return;
    int s = idx / HD, d = idx % HD;
    int i = d & 31;
    double invf = exp(-((double)(2 * i) / 64.0) * log(10000.0));
    double ang = (double)s * invf;
    g_emb[idx] = (float)((d < 32) ? sin(ang) : cos(ang));
}

// ---------------------------------------------------------------------------
// LayerNorm: one block per row, 256 threads, float4
// ---------------------------------------------------------------------------
__global__ __launch_bounds__(256) void ln_kernel(const float* __restrict__ x,
                                                 const float* __restrict__ gam,
                                                 const float* __restrict__ bet) {
    int row = blockIdx.x;
    const float4* xr = (const float4*)(x + (size_t)row * D_MODEL);
    float4 v = xr[threadIdx.x];
    float sum = v.x + v.y + v.z + v.w;
    float sq  = v.x*v.x + v.y*v.y + v.z*v.z + v.w*v.w;
    #pragma unroll
    for (int o = 16; o; o >>= 1) {
        sum += __shfl_xor_sync(0xFFFFFFFFu, sum, o);
        sq  += __shfl_xor_sync(0xFFFFFFFFu, sq, o);
    }
    __shared__ float ssum[8], ssq[8];
    int w = threadIdx.x >> 5, l = threadIdx.x & 31;
    if (!l) { ssum[w] = sum; ssq[w] = sq; }
    __syncthreads();
    if (w == 0) {
        sum = (l < 8) ? ssum[l] : 0.f;
        sq  = (l < 8) ? ssq[l]  : 0.f;
        #pragma unroll
        for (int o = 4; o; o >>= 1) {
            sum += __shfl_xor_sync(0xFFFFFFFFu, sum, o);
            sq  += __shfl_xor_sync(0xFFFFFFFFu, sq, o);
        }
        if (!l) { ssum[0] = sum; ssq[0] = sq; }
    }
    __syncthreads();
    float mu  = ssum[0] * (1.f / D_MODEL);
    float var = ssq[0] * (1.f / D_MODEL) - mu * mu;
    float rs  = rsqrtf(var + 1e-5f);
    int c = threadIdx.x * 4;
    float4 g4 = *(const float4*)(gam + c);
    float4 b4 = *(const float4*)(bet + c);
    float4 o;
    o.x = (v.x - mu) * rs * g4.x + b4.x;
    o.y = (v.y - mu) * rs * g4.y + b4.y;
    o.z = (v.z - mu) * rs * g4.z + b4.z;
    o.w = (v.w - mu) * rs * g4.w + b4.w;
    ((float4*)(g_xln + (size_t)row * D_MODEL))[threadIdx.x] = o;
}

// ---------------------------------------------------------------------------
// QKV projection GEMM: Y = Xln @ W^T, fused rotary + head-split epilogue.
// grid.x = 24 (n strips of 128 over 3072), grid.y = 64 (m strips of 128)
// ---------------------------------------------------------------------------
__global__ __launch_bounds__(256) void gemm_qkv(const float* __restrict__ qw,
                                                const float* __restrict__ kw,
                                                const float* __restrict__ vw) {
    __shared__ float As[16][132];
    __shared__ float Bs[16][132];
    const int tid = threadIdx.x;
    const int m0  = blockIdx.y * 128;
    const int n0g = blockIdx.x * 128;
    const int which = n0g >> 10;
    const int n0  = n0g & 1023;
    const float* __restrict__ W = (which == 0) ? qw : (which == 1) ? kw : vw;
    const float* __restrict__ A = g_xln;

    const int lr = tid >> 2;         // 0..63
    const int lc = (tid & 3) << 2;   // 0,4,8,12

    float acc[8][8];
    #pragma unroll
    for (int i = 0; i < 8; i++)
        #pragma unroll
        for (int j = 0; j < 8; j++) acc[i][j] = 0.f;

    for (int k0 = 0; k0 < D_MODEL; k0 += 16) {
        #pragma unroll
        for (int p = 0; p < 2; p++) {
            float4 av = *(const float4*)&A[(size_t)(m0 + lr + p * 64) * D_MODEL + k0 + lc];
            As[lc + 0][lr + p * 64] = av.x;
            As[lc + 1][lr + p * 64] = av.y;
            As[lc + 2][lr + p * 64] = av.z;
            As[lc + 3][lr + p * 64] = av.w;
            float4 bv = *(const float4*)&W[(size_t)(n0 + lr + p * 64) * D_MODEL + k0 + lc];
            Bs[lc + 0][lr + p * 64] = bv.x;
            Bs[lc + 1][lr + p * 64] = bv.y;
            Bs[lc + 2][lr + p * 64] = bv.z;
            Bs[lc + 3][lr + p * 64] = bv.w;
        }
        __syncthreads();
        const int tx = tid & 15, ty = tid >> 4;
        #pragma unroll
        for (int kk = 0; kk < 16; kk++) {
            float a[8], b[8];
            *(float4*)(a)     = *(const float4*)&As[kk][ty * 8];
            *(float4*)(a + 4) = *(const float4*)&As[kk][ty * 8 + 4];
            *(float4*)(b)     = *(const float4*)&Bs[kk][tx * 8];
            *(float4*)(b + 4) = *(const float4*)&Bs[kk][tx * 8 + 4];
            #pragma unroll
            for (int i = 0; i < 8; i++)
                #pragma unroll
                for (int j = 0; j < 8; j++) acc[i][j] += a[i] * b[j];
        }
        __syncthreads();
    }

    const int tx = tid & 15, ty = tid >> 4;
    float* __restrict__ dst = (which == 0) ? g_q : (which == 1) ? g_k : g_v;
    #pragma unroll
    for (int i = 0; i < 8; i++) {
        int m = m0 + ty * 8 + i;
        int b = m >> 11;       // / SEQ
        int s = m & 2047;
        #pragma unroll
        for (int jj = 0; jj < 8; jj += 4) {
            int n  = n0 + tx * 8 + jj;
            int h  = n >> 6;
            int dc = n & 63;
            float f0 = 1.f, f1 = 1.f, f2 = 1.f, f3 = 1.f;
            if (which < 2) {
                float4 e = *(const float4*)&g_emb[s * HD + dc];
                f0 = e.x; f1 = e.y; f2 = e.z; f3 = e.w;
            }
            float4 o;
            o.x = acc[i][jj + 0] * f0;
            o.y = acc[i][jj + 1] * f1;
            o.z = acc[i][jj + 2] * f2;
            o.w = acc[i][jj + 3] * f3;
            *(float4*)&dst[(size_t)((b * NHEAD + h) * SEQ + s) * HD + dc] = o;
        }
    }
}

// ---------------------------------------------------------------------------
// Flash attention, fp32. grid = (32 q-blocks, 64 b*h). 256 threads.
// Per thread: 4x4 score tile (ty=m-group, tx=n-group), 4x4 output tile.
// ---------------------------------------------------------------------------
__global__ __launch_bounds__(256) void attn_kernel(const unsigned char* __restrict__ kpm) {
    __shared__ float Qs[64][64];   // [kdim][m]  (transposed)
    __shared__ float KV[64][64];   // K phase: [kdim][n]; V phase: [n][dc]
    __shared__ float Ps[64][64];   // [m][n]

    const int tid = threadIdx.x;
    const int qb  = blockIdx.x;
    const int bh  = blockIdx.y;
    const int q0  = qb * 64;
    const int batch = bh >> 4;

    const float* __restrict__ Qg = g_q + (size_t)bh * SEQ * HD;
    const float* __restrict__ Kg = g_k + (size_t)bh * SEQ * HD;
    const float* __restrict__ Vg = g_v + (size_t)bh * SEQ * HD;
    const unsigned char* __restrict__ mask = kpm + (size_t)batch * SEQ;

    const int lr = tid >> 2;          // 0..63 (Q/K transpose loads)
    const int lc = (tid & 3) << 4;    // 0,16,32,48
    const int vr = tid >> 4;          // 0..15 (V direct loads)
    const int vc = (tid & 15) << 2;   // 0..60

    // load Q transposed (once)
    #pragma unroll
    for (int c = 0; c < 4; c++) {
        float4 v = *(const float4*)&Qg[(size_t)(q0 + lr) * HD + lc + c * 4];
        Qs[lc + c * 4 + 0][lr] = v.x;
        Qs[lc + c * 4 + 1][lr] = v.y;
        Qs[lc + c * 4 + 2][lr] = v.z;
        Qs[lc + c * 4 + 3][lr] = v.w;
    }

    const int tx = tid & 15, ty = tid >> 4;
    float acc[4][4];
    float mi[4], li[4];
    #pragma unroll
    for (int i = 0; i < 4; i++) {
        mi[i] = -INFINITY; li[i] = 0.f;
        #pragma unroll
        for (int j = 0; j < 4; j++) acc[i][j] = 0.f;
    }

    for (int kb = 0; kb <= qb; kb++) {
        const int kbase = kb * 64;
        __syncthreads();  // previous PV reads of KV complete
        // load K transposed
        #pragma unroll
        for (int c = 0; c < 4; c++) {
            float4 v = *(const float4*)&Kg[(size_t)(kbase + lr) * HD + lc + c * 4];
            KV[lc + c * 4 + 0][lr] = v.x;
            KV[lc + c * 4 + 1][lr] = v.y;
            KV[lc + c * 4 + 2][lr] = v.z;
            KV[lc + c * 4 + 3][lr] = v.w;
        }
        __syncthreads();  // K (and on iter0, Q) visible

        // S = Q @ K^T
        float s[4][4];
        #pragma unroll
        for (int i = 0; i < 4; i++)
            #pragma unroll
            for (int j = 0; j < 4; j++) s[i][j] = 0.f;
        #pragma unroll 16
        for (int kk = 0; kk < 64; kk++) {
            float4 a = *(const float4*)&Qs[kk][ty * 4];
            float4 b = *(const float4*)&KV[kk][tx * 4];
            float av[4] = {a.x, a.y, a.z, a.w};
            float bv[4] = {b.x, b.y, b.z, b.w};
            #pragma unroll
            for (int i = 0; i < 4; i++)
                #pragma unroll
                for (int j = 0; j < 4; j++) s[i][j] += av[i] * bv[j];
        }

        // scale + masks
        unsigned char mk[4];
        #pragma unroll
        for (int j = 0; j < 4; j++) mk[j] = mask[kbase + tx * 4 + j];
        const bool diag = (kb == qb);
        #pragma unroll
        for (int i = 0; i < 4; i++) {
            int qi = q0 + ty * 4 + i;
            #pragma unroll
            for (int j = 0; j < 4; j++) {
                int kj = kbase + tx * 4 + j;
                float v = s[i][j] * 0.125f;
                if ((diag && kj > qi) || mk[j]) v = -INFINITY;
                s[i][j] = v;
            }
        }

        // online softmax: row-max over j, then over the 16 tx lanes
        float mnew[4];
        #pragma unroll
        for (int i = 0; i < 4; i++) {
            mnew[i] = fmaxf(fmaxf(s[i][0], s[i][1]), fmaxf(s[i][2], s[i][3]));
        }
        #pragma unroll
        for (int o = 1; o < 16; o <<= 1)
            #pragma unroll
            for (int i = 0; i < 4; i++)
                mnew[i] = fmaxf(mnew[i], __shfl_xor_sync(0xFFFFFFFFu, mnew[i], o));

        float alpha[4], rowsum[4];
        #pragma unroll
        for (int i = 0; i < 4; i++) {
            float mt = fmaxf(mi[i], mnew[i]);
            alpha[i] = __expf(mi[i] - mt);
            mi[i] = mt;
            rowsum[i] = 0.f;
        }
        #pragma unroll
        for (int i = 0; i < 4; i++)
            #pragma unroll
            for (int j = 0; j < 4; j++) {
                float p = __expf(s[i][j] - mi[i]);
                s[i][j] = p;
                rowsum[i] += p;
            }
        #pragma unroll
        for (int o = 1; o < 16; o <<= 1)
            #pragma unroll
            for (int i = 0; i < 4; i++)
                rowsum[i] += __shfl_xor_sync(0xFFFFFFFFu, rowsum[i], o);
        #pragma unroll
        for (int i = 0; i < 4; i++) {
            li[i] = li[i] * alpha[i] + rowsum[i];
            #pragma unroll
            for (int j = 0; j < 4; j++) acc[i][j] *= alpha[i];
        }

        __syncthreads();  // score phase done reading KV

        // store P; load V into KV (direct [n][dc] layout)
        #pragma unroll
        for (int i = 0; i < 4; i++)
            #pragma unroll
            for (int j = 0; j < 4; j++)
                Ps[ty * 4 + i][tx * 4 + j] = s[i][j];
        #pragma unroll
        for (int r = 0; r < 4; r++) {
            int row = vr + r * 16;
            float4 v = *(const float4*)&Vg[(size_t)(kbase + row) * HD + vc];
            *(float4*)&KV[row][vc] = v;
        }
        __syncthreads();  // P + V visible

        // O += P @ V
        #pragma unroll 8
        for (int nn = 0; nn < 64; nn++) {
            float a0 = Ps[ty * 4 + 0][nn];
            float a1 = Ps[ty * 4 + 1][nn];
            float a2 = Ps[ty * 4 + 2][nn];
            float a3 = Ps[ty * 4 + 3][nn];
            float4 b = *(const float4*)&KV[nn][tx * 4];
            float bv[4] = {b.x, b.y, b.z, b.w};
            #pragma unroll
            for (int j = 0; j < 4; j++) {
                acc[0][j] += a0 * bv[j];
                acc[1][j] += a1 * bv[j];
                acc[2][j] += a2 * bv[j];
                acc[3][j] += a3 * bv[j];
            }
        }
    }

    // write ctx[b, s, h*64+dc] = acc / l
    const int h = bh & 15;
    #pragma unroll
    for (int i = 0; i < 4; i++) {
        float inv = 1.f / li[i];
        int sq = q0 + ty * 4 + i;
        float4 o;
        o.x = acc[i][0] * inv;
        o.y = acc[i][1] * inv;
        o.z = acc[i][2] * inv;
        o.w = acc[i][3] * inv;
        *(float4*)&g_ctx[(size_t)(batch * SEQ + sq) * D_MODEL + h * HD + tx * 4] = o;
    }
}

// ---------------------------------------------------------------------------
// Out projection GEMM + bias + residual: out = ctx @ Wo^T + bo + x
// grid = (8, 64)
// ---------------------------------------------------------------------------
__global__ __launch_bounds__(256) void gemm_out(const float* __restrict__ ow,
                                                const float* __restrict__ ob,
                                                const float* __restrict__ x,
                                                float* __restrict__ out) {
    __shared__ float As[16][132];
    __shared__ float Bs[16][132];
    const int tid = threadIdx.x;
    const int m0  = blockIdx.y * 128;
    const int n0  = blockIdx.x * 128;
    const float* __restrict__ A = g_ctx;

    const int lr = tid >> 2;
    const int lc = (tid & 3) << 2;

    float acc[8][8];
    #pragma unroll
    for (int i = 0; i < 8; i++)
        #pragma unroll
        for (int j = 0; j < 8; j++) acc[i][j] = 0.f;

    for (int k0 = 0; k0 < D_MODEL; k0 += 16) {
        #pragma unroll
        for (int p = 0; p < 2; p++) {
            float4 av = *(const float4*)&A[(size_t)(m0 + lr + p * 64) * D_MODEL + k0 + lc];
            As[lc + 0][lr + p * 64] = av.x;
            As[lc + 1][lr + p * 64] = av.y;
            As[lc + 2][lr + p * 64] = av.z;
            As[lc + 3][lr + p * 64] = av.w;
            float4 bv = *(const float4*)&ow[(size_t)(n0 + lr + p * 64) * D_MODEL + k0 + lc];
            Bs[lc + 0][lr + p * 64] = bv.x;
            Bs[lc + 1][lr + p * 64] = bv.y;
            Bs[lc + 2][lr + p * 64] = bv.z;
            Bs[lc + 3][lr + p * 64] = bv.w;
        }
        __syncthreads();
        const int tx = tid & 15, ty = tid >> 4;
        #pragma unroll
        for (int kk = 0; kk < 16; kk++) {
            float a[8], b[8];
            *(float4*)(a)     = *(const float4*)&As[kk][ty * 8];
            *(float4*)(a + 4) = *(const float4*)&As[kk][ty * 8 + 4];
            *(float4*)(b)     = *(const float4*)&Bs[kk][tx * 8];
            *(float4*)(b + 4) = *(const float4*)&Bs[kk][tx * 8 + 4];
            #pragma unroll
            for (int i = 0; i < 8; i++)
                #pragma unroll
                for (int j = 0; j < 8; j++) acc[i][j] += a[i] * b[j];
        }
        __syncthreads();
    }

    const int tx = tid & 15, ty = tid >> 4;
    #pragma unroll
    for (int i = 0; i < 8; i++) {
        int m = m0 + ty * 8 + i;
        #pragma unroll
        for (int jj = 0; jj < 8; jj += 4) {
            int n = n0 + tx * 8 + jj;
            float4 bb = *(const float4*)&ob[n];
            float4 xx = *(const float4*)&x[(size_t)m * D_MODEL + n];
            float4 o;
            o.x = acc[i][jj + 0] + bb.x + xx.x;
            o.y = acc[i][jj + 1] + bb.y + xx.y;
            o.z = acc[i][jj + 2] + bb.z + xx.z;
            o.w = acc[i][jj + 3] + bb.w + xx.w;
            *(float4*)&out[(size_t)m * D_MODEL + n] = o;
        }
    }
}

// ---------------------------------------------------------------------------
extern "C" void kernel_launch(void* const* d_in, const int* in_sizes, int n_in,
                              void* d_out, int out_size) {
    const float* x  = (const float*)d_in[0];
    const unsigned char* kpm = (const unsigned char*)d_in[1];
    const float* qw = (const float*)d_in[2];
    const float* kw = (const float*)d_in[3];
    const float* vw = (const float*)d_in[4];
    const float* ow = (const float*)d_in[5];
    const float* ob = (const float*)d_in[6];
    const float* lg = (const float*)d_in[7];
    const float* lb = (const float*)d_in[8];
    float* out = (float*)d_out;

    emb_kernel<<<(SEQ * HD + 255) / 256, 256>>>();
    ln_kernel<<<MTOT, 256>>>(x, lg, lb);
    gemm_qkv<<<dim3(24, 64), 256>>>(qw, kw, vw);
    attn_kernel<<<dim3(32, 64), 256>>>(kpm);
    gemm_out<<<dim3(8, 64), 256>>>(ow, ob, x, out);
}

// round 3
// speedup vs baseline: 1.5629x; 1.5629x over previous
#include <cuda_runtime.h>
#include <cstdint>
#include <math.h>

#define D_MODEL 1024
#define NHEAD   16
#define HD      64
#define SEQ     2048
#define BATCH   4
#define MTOT    (BATCH*SEQ)      // 8192
#define BHN     (BATCH*NHEAD)    // 64

static __device__ float g_xln[MTOT * D_MODEL];
static __device__ float g_q[BHN * SEQ * HD];
static __device__ float g_k[BHN * SEQ * HD];
static __device__ float g_v[BHN * SEQ * HD];
static __device__ float g_ctx[MTOT * D_MODEL];
static __device__ float g_emb[SEQ * HD];

// ---------------------------------------------------------------------------
// helpers: tf32 cvt, ldmatrix(x4 b16 trick for tf32), mma tf32
// ---------------------------------------------------------------------------
__device__ __forceinline__ uint32_t f2tf(float f) {
    uint32_t u;
    asm("cvt.rna.tf32.f32 %0, %1;" : "=r"(u) : "f"(f));
    return u;
}
__device__ __forceinline__ uint32_t sptr(const void* p) {
    return (uint32_t)__cvta_generic_to_shared(p);
}
__device__ __forceinline__ void ldsm4(uint32_t& r0, uint32_t& r1, uint32_t& r2, uint32_t& r3,
                                      uint32_t addr) {
    asm volatile("ldmatrix.sync.aligned.m8n8.x4.shared.b16 {%0,%1,%2,%3}, [%4];"
                 : "=r"(r0), "=r"(r1), "=r"(r2), "=r"(r3) : "r"(addr));
}
__device__ __forceinline__ void mma8(float* c, const uint32_t* a, uint32_t b0, uint32_t b1) {
    asm volatile("mma.sync.aligned.m16n8k8.row.col.f32.tf32.tf32.f32 "
                 "{%0,%1,%2,%3}, {%4,%5,%6,%7}, {%8,%9}, {%0,%1,%2,%3};"
                 : "+f"(c[0]), "+f"(c[1]), "+f"(c[2]), "+f"(c[3])
                 : "r"(a[0]), "r"(a[1]), "r"(a[2]), "r"(a[3]), "r"(b0), "r"(b1));
}

// ---------------------------------------------------------------------------
__global__ void emb_kernel() {
    int idx = blockIdx.x * blockDim.x + threadIdx.x;
    if (idx >= SEQ * HD) return;
    int s = idx / HD, d = idx % HD;
    int i = d & 31;
    double invf = exp(-((double)(2 * i) / 64.0) * log(10000.0));
    double ang = (double)s * invf;
    g_emb[idx] = (float)((d < 32) ? sin(ang) : cos(ang));
}

// ---------------------------------------------------------------------------
__global__ __launch_bounds__(256) void ln_kernel(const float* __restrict__ x,
                                                 const float* __restrict__ gam,
                                                 const float* __restrict__ bet) {
    int row = blockIdx.x;
    const float4* xr = (const float4*)(x + (size_t)row * D_MODEL);
    float4 v = xr[threadIdx.x];
    float sum = v.x + v.y + v.z + v.w;
    float sq  = v.x*v.x + v.y*v.y + v.z*v.z + v.w*v.w;
    #pragma unroll
    for (int o = 16; o; o >>= 1) {
        sum += __shfl_xor_sync(0xFFFFFFFFu, sum, o);
        sq  += __shfl_xor_sync(0xFFFFFFFFu, sq, o);
    }
    __shared__ float ssum[8], ssq[8];
    int w = threadIdx.x >> 5, l = threadIdx.x & 31;
    if (!l) { ssum[w] = sum; ssq[w] = sq; }
    __syncthreads();
    if (w == 0) {
        sum = (l < 8) ? ssum[l] : 0.f;
        sq  = (l < 8) ? ssq[l]  : 0.f;
        #pragma unroll
        for (int o = 4; o; o >>= 1) {
            sum += __shfl_xor_sync(0xFFFFFFFFu, sum, o);
            sq  += __shfl_xor_sync(0xFFFFFFFFu, sq, o);
        }
        if (!l) { ssum[0] = sum; ssq[0] = sq; }
    }
    __syncthreads();
    float mu  = ssum[0] * (1.f / D_MODEL);
    float var = ssq[0] * (1.f / D_MODEL) - mu * mu;
    float rs  = rsqrtf(var + 1e-5f);
    int c = threadIdx.x * 4;
    float4 g4 = *(const float4*)(gam + c);
    float4 b4 = *(const float4*)(bet + c);
    float4 o;
    o.x = (v.x - mu) * rs * g4.x + b4.x;
    o.y = (v.y - mu) * rs * g4.y + b4.y;
    o.z = (v.z - mu) * rs * g4.z + b4.z;
    o.w = (v.w - mu) * rs * g4.w + b4.w;
    ((float4*)(g_xln + (size_t)row * D_MODEL))[threadIdx.x] = o;
}

// ---------------------------------------------------------------------------
// tf32 GEMM core: CTA 128x128, K staged 32/iter, 8 warps (2m x 4n), warp 64x32
// acc[mt][nt][4], mt 0..3 (m16), nt 0..3 (n8)
// ---------------------------------------------------------------------------
struct GemmAcc { float a[4][4][4]; };

__device__ __forceinline__ void gemm_core(const float* __restrict__ A,
                                          const float* __restrict__ B,
                                          int m0, int n0, GemmAcc& G,
                                          uint32_t (*As)[36], uint32_t (*Bs)[36]) {
    const int tid  = threadIdx.x;
    const int lane = tid & 31, warp = tid >> 5;
    const int wm = warp >> 2, wn = warp & 3;

    #pragma unroll
    for (int mt = 0; mt < 4; mt++)
        #pragma unroll
        for (int nt = 0; nt < 4; nt++)
            #pragma unroll
            for (int j = 0; j < 4; j++) G.a[mt][nt][j] = 0.f;

    const int lrow = tid >> 1;
    const int lcol = (tid & 1) << 4;
    const float* ap = A + (size_t)(m0 + lrow) * D_MODEL + lcol;
    const float* bp = B + (size_t)(n0 + lrow) * D_MODEL + lcol;

    float4 ra[4], rb[4];
    #pragma unroll
    for (int i = 0; i < 4; i++) { ra[i] = *(const float4*)(ap + i * 4); rb[i] = *(const float4*)(bp + i * 4); }

    const int g = lane >> 3, r = lane & 7;

    for (int kt = 0; kt < 32; kt++) {
        #pragma unroll
        for (int i = 0; i < 4; i++) {
            uint4 ua = { f2tf(ra[i].x), f2tf(ra[i].y), f2tf(ra[i].z), f2tf(ra[i].w) };
            *(uint4*)&As[lrow][lcol + i * 4] = ua;
            uint4 ub = { f2tf(rb[i].x), f2tf(rb[i].y), f2tf(rb[i].z), f2tf(rb[i].w) };
            *(uint4*)&Bs[lrow][lcol + i * 4] = ub;
        }
        __syncthreads();
        if (kt < 31) {
            ap += 32; bp += 32;
            #pragma unroll
            for (int i = 0; i < 4; i++) { ra[i] = *(const float4*)(ap + i * 4); rb[i] = *(const float4*)(bp + i * 4); }
        }
        #pragma unroll
        for (int ks = 0; ks < 4; ks++) {
            const int kk = ks * 8;
            uint32_t af[4][4];
            #pragma unroll
            for (int mt = 0; mt < 4; mt++) {
                int row = wm * 64 + mt * 16 + (g & 1) * 8 + r;
                int col = kk + (g >> 1) * 4;
                ldsm4(af[mt][0], af[mt][1], af[mt][2], af[mt][3], sptr(&As[row][col]));
            }
            uint32_t bf[4][2];
            #pragma unroll
            for (int np = 0; np < 2; np++) {
                int nt  = np * 2 + (g >> 1);
                int row = wn * 32 + nt * 8 + r;
                int col = kk + (g & 1) * 4;
                uint32_t t0, t1, t2, t3;
                ldsm4(t0, t1, t2, t3, sptr(&Bs[row][col]));
                bf[np * 2][0] = t0; bf[np * 2][1] = t1;
                bf[np * 2 + 1][0] = t2; bf[np * 2 + 1][1] = t3;
            }
            #pragma unroll
            for (int mt = 0; mt < 4; mt++)
                #pragma unroll
                for (int nt = 0; nt < 4; nt++)
                    mma8(G.a[mt][nt], af[mt], bf[nt][0], bf[nt][1]);
        }
        __syncthreads();
    }
}

// ---------------------------------------------------------------------------
// QKV proj: grid (24, 64); bx>>3 selects weight, rotary + head-split epilogue
// ---------------------------------------------------------------------------
__global__ __launch_bounds__(256) void gemm_qkv(const float* __restrict__ qw,
                                                const float* __restrict__ kw,
                                                const float* __restrict__ vw) {
    __shared__ uint32_t As[128][36];
    __shared__ uint32_t Bs[128][36];
    const int m0 = blockIdx.y * 128;
    const int which = blockIdx.x >> 3;
    const int n0 = (blockIdx.x & 7) * 128;
    const float* W = (which == 0) ? qw : (which == 1) ? kw : vw;

    GemmAcc G;
    gemm_core(g_xln, W, m0, n0, G, As, Bs);

    const int lane = threadIdx.x & 31, warp = threadIdx.x >> 5;
    const int wm = warp >> 2, wn = warp & 3;
    float* dst = (which == 0) ? g_q : (which == 1) ? g_k : g_v;

    #pragma unroll
    for (int mt = 0; mt < 4; mt++) {
        #pragma unroll
        for (int rh = 0; rh < 2; rh++) {
            int m = m0 + wm * 64 + mt * 16 + rh * 8 + (lane >> 2);
            int b = m >> 11, s = m & 2047;
            #pragma unroll
            for (int nt = 0; nt < 4; nt++) {
                int n  = n0 + wn * 32 + nt * 8 + (lane & 3) * 2;
                int h  = n >> 6, dc = n & 63;
                float ex = 1.f, ey = 1.f;
                if (which < 2) {
                    float2 e = *(const float2*)&g_emb[s * HD + dc];
                    ex = e.x; ey = e.y;
                }
                float2 o;
                o.x = G.a[mt][nt][rh * 2 + 0] * ex;
                o.y = G.a[mt][nt][rh * 2 + 1] * ey;
                *(float2*)&dst[((size_t)(b * NHEAD + h) * SEQ + s) * HD + dc] = o;
            }
        }
    }
}

// ---------------------------------------------------------------------------
// out proj + bias + residual: grid (8, 64)
// ---------------------------------------------------------------------------
__global__ __launch_bounds__(256) void gemm_out(const float* __restrict__ ow,
                                                const float* __restrict__ ob,
                                                const float* __restrict__ x,
                                                float* __restrict__ out) {
    __shared__ uint32_t As[128][36];
    __shared__ uint32_t Bs[128][36];
    const int m0 = blockIdx.y * 128;
    const int n0 = blockIdx.x * 128;

    GemmAcc G;
    gemm_core(g_ctx, ow, m0, n0, G, As, Bs);

    const int lane = threadIdx.x & 31, warp = threadIdx.x >> 5;
    const int wm = warp >> 2, wn = warp & 3;

    #pragma unroll
    for (int mt = 0; mt < 4; mt++) {
        #pragma unroll
        for (int rh = 0; rh < 2; rh++) {
            int m = m0 + wm * 64 + mt * 16 + rh * 8 + (lane >> 2);
            #pragma unroll
            for (int nt = 0; nt < 4; nt++) {
                int n = n0 + wn * 32 + nt * 8 + (lane & 3) * 2;
                float2 bb = *(const float2*)&ob[n];
                float2 xx = *(const float2*)&x[(size_t)m * D_MODEL + n];
                float2 o;
                o.x = G.a[mt][nt][rh * 2 + 0] + bb.x + xx.x;
                o.y = G.a[mt][nt][rh * 2 + 1] + bb.y + xx.y;
                *(float2*)&out[(size_t)m * D_MODEL + n] = o;
            }
        }
    }
}

// ---------------------------------------------------------------------------
// Flash attention, tf32 mma. grid (16 q-blocks of 128, 64 b*h). 256 threads.
// warp w owns rows q0 + w*16 .. +15, full 64-col K blocks.
// ---------------------------------------------------------------------------
__global__ __launch_bounds__(256) void attn_kernel(const unsigned char* __restrict__ kpm) {
    __shared__ uint32_t Ks[64][68];   // [key-row][d]   (k-contig for B frags)
    __shared__ uint32_t Vt[64][68];   // [d][key-row]   (transposed V)

    const int tid = threadIdx.x, lane = tid & 31, warp = tid >> 5;
    const int qb = blockIdx.x, bh = blockIdx.y;
    const int q0 = qb * 128;
    const int batch = bh >> 4, h = bh & 15;

    const float* __restrict__ Qg = g_q + (size_t)bh * SEQ * HD;
    const float* __restrict__ Kg = g_k + (size_t)bh * SEQ * HD;
    const float* __restrict__ Vg = g_v + (size_t)bh * SEQ * HD;
    const unsigned char* __restrict__ maskp = kpm + (size_t)batch * SEQ;

    // Q fragments (persistent, scaled by 1/8): qf[ktile][4]
    uint32_t qf[8][4];
    {
        const int r0 = q0 + warp * 16 + (lane >> 2);
        #pragma unroll
        for (int t = 0; t < 8; t++) {
            int c = t * 8 + (lane & 3);
            qf[t][0] = f2tf(0.125f * Qg[(size_t)r0 * HD + c]);
            qf[t][1] = f2tf(0.125f * Qg[(size_t)(r0 + 8) * HD + c]);
            qf[t][2] = f2tf(0.125f * Qg[(size_t)r0 * HD + c + 4]);
            qf[t][3] = f2tf(0.125f * Qg[(size_t)(r0 + 8) * HD + c + 4]);
        }
    }

    float o[8][4];
    #pragma unroll
    for (int nt = 0; nt < 8; nt++)
        #pragma unroll
        for (int j = 0; j < 4; j++) o[nt][j] = 0.f;
    float mi0 = -INFINITY, mi1 = -INFINITY, li0 = 0.f, li1 = 0.f;

    const int nkb = 2 * qb + 2;
    const int krow = tid >> 2, kcb = (tid & 3) << 4;   // K loads
    const int vrow = tid & 63, vcb = (tid >> 6) << 4;  // V loads (for transpose)
    const int g = lane >> 3, r = lane & 7;

    float4 rk[4], rv[4];
    #pragma unroll
    for (int i = 0; i < 4; i++) {
        rk[i] = *(const float4*)&Kg[(size_t)krow * HD + kcb + i * 4];
        rv[i] = *(const float4*)&Vg[(size_t)vrow * HD + vcb + i * 4];
    }

    for (int kb = 0; kb < nkb; kb++) {
        const int kbase = kb * 64;
        __syncthreads();
        #pragma unroll
        for (int i = 0; i < 4; i++) {
            uint4 uk = { f2tf(rk[i].x), f2tf(rk[i].y), f2tf(rk[i].z), f2tf(rk[i].w) };
            *(uint4*)&Ks[krow][kcb + i * 4] = uk;
            Vt[vcb + i * 4 + 0][vrow] = f2tf(rv[i].x);
            Vt[vcb + i * 4 + 1][vrow] = f2tf(rv[i].y);
            Vt[vcb + i * 4 + 2][vrow] = f2tf(rv[i].z);
            Vt[vcb + i * 4 + 3][vrow] = f2tf(rv[i].w);
        }
        __syncthreads();
        if (kb + 1 < nkb) {
            const int nb = kbase + 64;
            #pragma unroll
            for (int i = 0; i < 4; i++) {
                rk[i] = *(const float4*)&Kg[(size_t)(nb + krow) * HD + kcb + i * 4];
                rv[i] = *(const float4*)&Vg[(size_t)(nb + vrow) * HD + vcb + i * 4];
            }
        }

        const bool active = (kbase <= q0 + warp * 16 + 15);
        if (active) {
            // S = Q K^T (scaled)
            float s[8][4];
            #pragma unroll
            for (int nt = 0; nt < 8; nt++)
                #pragma unroll
                for (int j = 0; j < 4; j++) s[nt][j] = 0.f;
            #pragma unroll
            for (int ks = 0; ks < 8; ks++) {
                const int kk = ks * 8;
                #pragma unroll
                for (int np = 0; np < 4; np++) {
                    int nt = np * 2 + (g >> 1);
                    uint32_t t0, t1, t2, t3;
                    ldsm4(t0, t1, t2, t3, sptr(&Ks[nt * 8 + r][kk + (g & 1) * 4]));
                    mma8(s[np * 2], qf[ks], t0, t1);
                    mma8(s[np * 2 + 1], qf[ks], t2, t3);
                }
            }

            // masks
            const int row0 = q0 + warp * 16 + (lane >> 2);
            const bool needc = (kbase + 63) > (q0 + warp * 16);
            #pragma unroll
            for (int nt = 0; nt < 8; nt++) {
                int c = nt * 8 + (lane & 3) * 2;
                unsigned char mb0 = maskp[kbase + c], mb1 = maskp[kbase + c + 1];
                if (mb0) { s[nt][0] = -INFINITY; s[nt][2] = -INFINITY; }
                if (mb1) { s[nt][1] = -INFINITY; s[nt][3] = -INFINITY; }
                if (needc) {
                    int cg = kbase + c;
                    if (cg     > row0)     s[nt][0] = -INFINITY;
                    if (cg + 1 > row0)     s[nt][1] = -INFINITY;
                    if (cg     > row0 + 8) s[nt][2] = -INFINITY;
                    if (cg + 1 > row0 + 8) s[nt][3] = -INFINITY;
                }
            }

            // online softmax (two row-halves per thread, quad = lanes sharing row)
            float mx0 = -INFINITY, mx1 = -INFINITY;
            #pragma unroll
            for (int nt = 0; nt < 8; nt++) {
                mx0 = fmaxf(mx0, fmaxf(s[nt][0], s[nt][1]));
                mx1 = fmaxf(mx1, fmaxf(s[nt][2], s[nt][3]));
            }
            mx0 = fmaxf(mx0, __shfl_xor_sync(0xFFFFFFFFu, mx0, 1));
            mx0 = fmaxf(mx0, __shfl_xor_sync(0xFFFFFFFFu, mx0, 2));
            mx1 = fmaxf(mx1, __shfl_xor_sync(0xFFFFFFFFu, mx1, 1));
            mx1 = fmaxf(mx1, __shfl_xor_sync(0xFFFFFFFFu, mx1, 2));
            float mt0 = fmaxf(mi0, mx0), mt1 = fmaxf(mi1, mx1);
            float ms0 = (mt0 == -INFINITY) ? 0.f : mt0;
            float ms1 = (mt1 == -INFINITY) ? 0.f : mt1;
            float al0 = __expf(mi0 - ms0), al1 = __expf(mi1 - ms1);
            mi0 = mt0; mi1 = mt1;
            float rs0 = 0.f, rs1 = 0.f;
            #pragma unroll
            for (int nt = 0; nt < 8; nt++) {
                s[nt][0] = __expf(s[nt][0] - ms0); rs0 += s[nt][0];
                s[nt][1] = __expf(s[nt][1] - ms0); rs0 += s[nt][1];
                s[nt][2] = __expf(s[nt][2] - ms1); rs1 += s[nt][2];
                s[nt][3] = __expf(s[nt][3] - ms1); rs1 += s[nt][3];
            }
            rs0 += __shfl_xor_sync(0xFFFFFFFFu, rs0, 1);
            rs0 += __shfl_xor_sync(0xFFFFFFFFu, rs0, 2);
            rs1 += __shfl_xor_sync(0xFFFFFFFFu, rs1, 1);
            rs1 += __shfl_xor_sync(0xFFFFFFFFu, rs1, 2);
            li0 = li0 * al0 + rs0;
            li1 = li1 * al1 + rs1;
            #pragma unroll
            for (int nt = 0; nt < 8; nt++) {
                o[nt][0] *= al0; o[nt][1] *= al0;
                o[nt][2] *= al1; o[nt][3] *= al1;
            }

            // P accum-layout -> A-fragment via quad shuffles, then O += P V
            uint32_t pi[8][4];
            #pragma unroll
            for (int nt = 0; nt < 8; nt++)
                #pragma unroll
                for (int j = 0; j < 4; j++) pi[nt][j] = f2tf(s[nt][j]);

            const int c   = lane & 3;
            const int srcA = (lane & ~3) | (c >> 1);
            const int srcC = srcA + 2;
            const bool odd = (c & 1);

            #pragma unroll
            for (int t = 0; t < 8; t++) {
                uint32_t pa[4];
                {
                    uint32_t l0 = __shfl_sync(0xFFFFFFFFu, pi[t][0], srcA);
                    uint32_t h0 = __shfl_sync(0xFFFFFFFFu, pi[t][1], srcA);
                    pa[0] = odd ? h0 : l0;
                    uint32_t l1 = __shfl_sync(0xFFFFFFFFu, pi[t][2], srcA);
                    uint32_t h1 = __shfl_sync(0xFFFFFFFFu, pi[t][3], srcA);
                    pa[1] = odd ? h1 : l1;
                    uint32_t l2 = __shfl_sync(0xFFFFFFFFu, pi[t][0], srcC);
                    uint32_t h2 = __shfl_sync(0xFFFFFFFFu, pi[t][1], srcC);
                    pa[2] = odd ? h2 : l2;
                    uint32_t l3 = __shfl_sync(0xFFFFFFFFu, pi[t][2], srcC);
                    uint32_t h3 = __shfl_sync(0xFFFFFFFFu, pi[t][3], srcC);
                    pa[3] = odd ? h3 : l3;
                }
                #pragma unroll
                for (int np = 0; np < 4; np++) {
                    int nt = np * 2 + (g >> 1);
                    uint32_t t0, t1, t2, t3;
                    ldsm4(t0, t1, t2, t3, sptr(&Vt[nt * 8 + r][t * 8 + (g & 1) * 4]));
                    mma8(o[np * 2], pa, t0, t1);
                    mma8(o[np * 2 + 1], pa, t2, t3);
                }
            }
        }
    }

    // epilogue: normalize + write ctx[b, s, h*64+dc]
    const float inv0 = 1.f / li0, inv1 = 1.f / li1;
    const int r0 = q0 + warp * 16 + (lane >> 2);
    #pragma unroll
    for (int nt = 0; nt < 8; nt++) {
        int dc = nt * 8 + (lane & 3) * 2;
        float2 w0 = { o[nt][0] * inv0, o[nt][1] * inv0 };
        float2 w1 = { o[nt][2] * inv1, o[nt][3] * inv1 };
        *(float2*)&g_ctx[(size_t)(batch * SEQ + r0) * D_MODEL + h * HD + dc] = w0;
        *(float2*)&g_ctx[(size_t)(batch * SEQ + r0 + 8) * D_MODEL + h * HD + dc] = w1;
    }
}

// ---------------------------------------------------------------------------
extern "C" void kernel_launch(void* const* d_in, const int* in_sizes, int n_in,
                              void* d_out, int out_size) {
    const float* x  = (const float*)d_in[0];
    const unsigned char* kpm = (const unsigned char*)d_in[1];
    const float* qw = (const float*)d_in[2];
    const float* kw = (const float*)d_in[3];
    const float* vw = (const float*)d_in[4];
    const float* ow = (const float*)d_in[5];
    const float* ob = (const float*)d_in[6];
    const float* lg = (const float*)d_in[7];
    const float* lb = (const float*)d_in[8];
    float* out = (float*)d_out;

    emb_kernel<<<(SEQ * HD + 255) / 256, 256>>>();
    ln_kernel<<<MTOT, 256>>>(x, lg, lb);
    gemm_qkv<<<dim3(24, 64), 256>>>(qw, kw, vw);
    attn_kernel<<<dim3(16, 64), 256>>>(kpm);
    gemm_out<<<dim3(8, 64), 256>>>(ow, ob, x, out);
}

// round 4
// speedup vs baseline: 5.3954x; 3.4521x over previous
#include <cuda_runtime.h>
#include <cuda_bf16.h>
#include <cstdint>
#include <math.h>

#define D_MODEL 1024
#define NHEAD   16
#define HD      64
#define SEQ     2048
#define BATCH   4
#define MTOT    (BATCH*SEQ)      // 8192
#define BHN     (BATCH*NHEAD)    // 64

static __device__ __nv_bfloat16 g_xln[MTOT * D_MODEL];
static __device__ __nv_bfloat16 g_q[BHN * SEQ * HD];
static __device__ __nv_bfloat16 g_k[BHN * SEQ * HD];
static __device__ __nv_bfloat16 g_v[BHN * SEQ * HD];
static __device__ __nv_bfloat16 g_ctx[MTOT * D_MODEL];
static __device__ __nv_bfloat16 g_wq[D_MODEL * D_MODEL];
static __device__ __nv_bfloat16 g_wk[D_MODEL * D_MODEL];
static __device__ __nv_bfloat16 g_wv[D_MODEL * D_MODEL];
static __device__ __nv_bfloat16 g_wo[D_MODEL * D_MODEL];
static __device__ float g_emb[SEQ * HD];

// ---------------------------------------------------------------------------
// helpers
// ---------------------------------------------------------------------------
__device__ __forceinline__ uint32_t sptr(const void* p) {
    return (uint32_t)__cvta_generic_to_shared(p);
}
__device__ __forceinline__ uint32_t pack_bf16(float lo, float hi) {
    uint32_t d;
    asm("cvt.rn.bf16x2.f32 %0, %1, %2;" : "=r"(d) : "f"(hi), "f"(lo));
    return d;
}
__device__ __forceinline__ void ldsm4(uint32_t& r0, uint32_t& r1, uint32_t& r2, uint32_t& r3,
                                      uint32_t addr) {
    asm volatile("ldmatrix.sync.aligned.m8n8.x4.shared.b16 {%0,%1,%2,%3}, [%4];"
                 : "=r"(r0), "=r"(r1), "=r"(r2), "=r"(r3) : "r"(addr));
}
__device__ __forceinline__ void ldsm4t(uint32_t& r0, uint32_t& r1, uint32_t& r2, uint32_t& r3,
                                       uint32_t addr) {
    asm volatile("ldmatrix.sync.aligned.m8n8.x4.trans.shared.b16 {%0,%1,%2,%3}, [%4];"
                 : "=r"(r0), "=r"(r1), "=r"(r2), "=r"(r3) : "r"(addr));
}
__device__ __forceinline__ void mma16(float* c, const uint32_t* a, uint32_t b0, uint32_t b1) {
    asm volatile("mma.sync.aligned.m16n8k16.row.col.f32.bf16.bf16.f32 "
                 "{%0,%1,%2,%3}, {%4,%5,%6,%7}, {%8,%9}, {%0,%1,%2,%3};"
                 : "+f"(c[0]), "+f"(c[1]), "+f"(c[2]), "+f"(c[3])
                 : "r"(a[0]), "r"(a[1]), "r"(a[2]), "r"(a[3]), "r"(b0), "r"(b1));
}
__device__ __forceinline__ void cpa16(uint32_t dst, const void* src) {
    asm volatile("cp.async.cg.shared.global [%0], [%1], 16;" :: "r"(dst), "l"(src));
}
__device__ __forceinline__ void cp_commit() { asm volatile("cp.async.commit_group;"); }
template<int N> __device__ __forceinline__ void cp_wait() {
    asm volatile("cp.async.wait_group %0;" :: "n"(N));
}

// ---------------------------------------------------------------------------
__global__ void emb_kernel() {
    int idx = blockIdx.x * blockDim.x + threadIdx.x;
    if (idx >= SEQ * HD) return;
    int s = idx / HD, d = idx % HD;
    int i = d & 31;
    double invf = exp(-((double)(2 * i) / 64.0) * log(10000.0));
    double ang = (double)s * invf;
    g_emb[idx] = (float)((d < 32) ? sin(ang) : cos(ang));
}

// weight fp32 -> bf16
__global__ __launch_bounds__(256) void wcvt_kernel(const float* __restrict__ src,
                                                   __nv_bfloat16* __restrict__ dst) {
    int i = (blockIdx.x * 256 + threadIdx.x) * 4;
    float4 v = *(const float4*)(src + i);
    uint2 o;
    o.x = pack_bf16(v.x, v.y);
    o.y = pack_bf16(v.z, v.w);
    *(uint2*)(dst + i) = o;
}

// ---------------------------------------------------------------------------
__global__ __launch_bounds__(256) void ln_kernel(const float* __restrict__ x,
                                                 const float* __restrict__ gam,
                                                 const float* __restrict__ bet) {
    int row = blockIdx.x;
    const float4* xr = (const float4*)(x + (size_t)row * D_MODEL);
    float4 v = xr[threadIdx.x];
    float sum = v.x + v.y + v.z + v.w;
    float sq  = v.x*v.x + v.y*v.y + v.z*v.z + v.w*v.w;
    #pragma unroll
    for (int o = 16; o; o >>= 1) {
        sum += __shfl_xor_sync(0xFFFFFFFFu, sum, o);
        sq  += __shfl_xor_sync(0xFFFFFFFFu, sq, o);
    }
    __shared__ float ssum[8], ssq[8];
    int w = threadIdx.x >> 5, l = threadIdx.x & 31;
    if (!l) { ssum[w] = sum; ssq[w] = sq; }
    __syncthreads();
    if (w == 0) {
        sum = (l < 8) ? ssum[l] : 0.f;
        sq  = (l < 8) ? ssq[l]  : 0.f;
        #pragma unroll
        for (int o = 4; o; o >>= 1) {
            sum += __shfl_xor_sync(0xFFFFFFFFu, sum, o);
            sq  += __shfl_xor_sync(0xFFFFFFFFu, sq, o);
        }
        if (!l) { ssum[0] = sum; ssq[0] = sq; }
    }
    __syncthreads();
    float mu  = ssum[0] * (1.f / D_MODEL);
    float var = ssq[0] * (1.f / D_MODEL) - mu * mu;
    float rs  = rsqrtf(var + 1e-5f);
    int c = threadIdx.x * 4;
    float4 g4 = *(const float4*)(gam + c);
    float4 b4 = *(const float4*)(bet + c);
    uint2 o;
    o.x = pack_bf16((v.x - mu) * rs * g4.x + b4.x, (v.y - mu) * rs * g4.y + b4.y);
    o.y = pack_bf16((v.z - mu) * rs * g4.z + b4.z, (v.w - mu) * rs * g4.w + b4.w);
    *(uint2*)(g_xln + (size_t)row * D_MODEL + c) = o;
}

// ---------------------------------------------------------------------------
// bf16 GEMM core: CTA 128x128, k-stage 32, double-buffered cp.async.
// 8 warps (2m x 4n), warp 64x32, mma m16n8k16.
// ---------------------------------------------------------------------------
struct GemmAcc { float a[4][4][4]; };

__device__ __forceinline__ void gemm_core(const __nv_bfloat16* __restrict__ A,
                                          const __nv_bfloat16* __restrict__ B,
                                          int m0, int n0, GemmAcc& G) {
    __shared__ __align__(16) __nv_bfloat16 Asb[2][128][40];
    __shared__ __align__(16) __nv_bfloat16 Bsb[2][128][40];

    const int tid  = threadIdx.x;
    const int lane = tid & 31, warp = tid >> 5;
    const int wm = warp >> 2, wn = warp & 3;

    #pragma unroll
    for (int mt = 0; mt < 4; mt++)
        #pragma unroll
        for (int nt = 0; nt < 4; nt++)
            #pragma unroll
            for (int j = 0; j < 4; j++) G.a[mt][nt][j] = 0.f;

    const int c0 = tid, c1 = tid + 256;
    const int r0c = c0 >> 2, k0c = (c0 & 3) * 8;
    const int r1c = c1 >> 2, k1c = (c1 & 3) * 8;

    auto issue = [&](int st, int k0) {
        cpa16(sptr(&Asb[st][r0c][k0c]), A + (size_t)(m0 + r0c) * D_MODEL + k0 + k0c);
        cpa16(sptr(&Asb[st][r1c][k1c]), A + (size_t)(m0 + r1c) * D_MODEL + k0 + k1c);
        cpa16(sptr(&Bsb[st][r0c][k0c]), B + (size_t)(n0 + r0c) * D_MODEL + k0 + k0c);
        cpa16(sptr(&Bsb[st][r1c][k1c]), B + (size_t)(n0 + r1c) * D_MODEL + k0 + k1c);
        cp_commit();
    };

    issue(0, 0);

    // ldmatrix lane addressing
    const int arow = (lane & 15);
    const int ahi  = (lane >> 4) * 8;          // A k-offset
    const int brow = ((lane >> 4) & 1) * 8 + (lane & 7);
    const int bhi  = ((lane >> 3) & 1) * 8;    // B k-offset

    for (int kt = 0; kt < 32; kt++) {
        const int st = kt & 1;
        if (kt + 1 < 32) issue(st ^ 1, (kt + 1) * 32);
        if (kt + 1 < 32) cp_wait<1>(); else cp_wait<0>();
        __syncthreads();

        #pragma unroll
        for (int ks = 0; ks < 2; ks++) {
            const int kk = ks * 16;
            uint32_t af[4][4];
            #pragma unroll
            for (int mt = 0; mt < 4; mt++)
                ldsm4(af[mt][0], af[mt][1], af[mt][2], af[mt][3],
                      sptr(&Asb[st][wm * 64 + mt * 16 + arow][kk + ahi]));
            uint32_t bf[4][2];
            #pragma unroll
            for (int np = 0; np < 2; np++) {
                uint32_t t0, t1, t2, t3;
                ldsm4(t0, t1, t2, t3,
                      sptr(&Bsb[st][wn * 32 + np * 16 + brow][kk + bhi]));
                bf[np * 2][0] = t0;     bf[np * 2][1] = t1;
                bf[np * 2 + 1][0] = t2; bf[np * 2 + 1][1] = t3;
            }
            #pragma unroll
            for (int mt = 0; mt < 4; mt++)
                #pragma unroll
                for (int nt = 0; nt < 4; nt++)
                    mma16(G.a[mt][nt], af[mt], bf[nt][0], bf[nt][1]);
        }
        __syncthreads();
    }
}

// ---------------------------------------------------------------------------
// QKV proj: grid (24, 64). Fused rotary (+0.125 scale on q) + head-split.
// ---------------------------------------------------------------------------
__global__ __launch_bounds__(256, 2) void gemm_qkv() {
    const int m0 = blockIdx.y * 128;
    const int which = blockIdx.x >> 3;
    const int n0 = (blockIdx.x & 7) * 128;
    const __nv_bfloat16* W = (which == 0) ? g_wq : (which == 1) ? g_wk : g_wv;

    GemmAcc G;
    gemm_core(g_xln, W, m0, n0, G);

    const int lane = threadIdx.x & 31, warp = threadIdx.x >> 5;
    const int wm = warp >> 2, wn = warp & 3;
    __nv_bfloat16* dst = (which == 0) ? g_q : (which == 1) ? g_k : g_v;

    #pragma unroll
    for (int mt = 0; mt < 4; mt++) {
        #pragma unroll
        for (int rh = 0; rh < 2; rh++) {
            int m = m0 + wm * 64 + mt * 16 + rh * 8 + (lane >> 2);
            int b = m >> 11, s = m & 2047;
            #pragma unroll
            for (int nt = 0; nt < 4; nt++) {
                int n  = n0 + wn * 32 + nt * 8 + (lane & 3) * 2;
                int h  = n >> 6, dc = n & 63;
                float ex = 1.f, ey = 1.f;
                if (which < 2) {
                    float2 e = *(const float2*)&g_emb[s * HD + dc];
                    ex = e.x; ey = e.y;
                    if (which == 0) { ex *= 0.125f; ey *= 0.125f; }
                }
                uint32_t o = pack_bf16(G.a[mt][nt][rh * 2 + 0] * ex,
                                       G.a[mt][nt][rh * 2 + 1] * ey);
                *(uint32_t*)&dst[((size_t)(b * NHEAD + h) * SEQ + s) * HD + dc] = o;
            }
        }
    }
}

// ---------------------------------------------------------------------------
// out proj + bias + residual: grid (8, 64)
// ---------------------------------------------------------------------------
__global__ __launch_bounds__(256, 2) void gemm_out(const float* __restrict__ ob,
                                                   const float* __restrict__ x,
                                                   float* __restrict__ out) {
    const int m0 = blockIdx.y * 128;
    const int n0 = blockIdx.x * 128;

    GemmAcc G;
    gemm_core(g_ctx, g_wo, m0, n0, G);

    const int lane = threadIdx.x & 31, warp = threadIdx.x >> 5;
    const int wm = warp >> 2, wn = warp & 3;

    #pragma unroll
    for (int mt = 0; mt < 4; mt++) {
        #pragma unroll
        for (int rh = 0; rh < 2; rh++) {
            int m = m0 + wm * 64 + mt * 16 + rh * 8 + (lane >> 2);
            #pragma unroll
            for (int nt = 0; nt < 4; nt++) {
                int n = n0 + wn * 32 + nt * 8 + (lane & 3) * 2;
                float2 bb = *(const float2*)&ob[n];
                float2 xx = *(const float2*)&x[(size_t)m * D_MODEL + n];
                float2 o;
                o.x = G.a[mt][nt][rh * 2 + 0] + bb.x + xx.x;
                o.y = G.a[mt][nt][rh * 2 + 1] + bb.y + xx.y;
                *(float2*)&out[(size_t)m * D_MODEL + n] = o;
            }
        }
    }
}

// ---------------------------------------------------------------------------
// Flash attention, bf16 mma. grid (16 q-blocks of 128, 64 b*h). 256 threads.
// ---------------------------------------------------------------------------
__global__ __launch_bounds__(256, 2) void attn_kernel(const unsigned char* __restrict__ kpm) {
    __shared__ __align__(16) __nv_bfloat16 Ks[2][64][72];
    __shared__ __align__(16) __nv_bfloat16 Vs[2][64][72];

    const int tid = threadIdx.x, lane = tid & 31, warp = tid >> 5;
    const int qb = blockIdx.x, bh = blockIdx.y;
    const int q0 = qb * 128;
    const int batch = bh >> 4, h = bh & 15;

    const __nv_bfloat16* __restrict__ Qg = g_q + (size_t)bh * SEQ * HD;
    const __nv_bfloat16* __restrict__ Kg = g_k + (size_t)bh * SEQ * HD;
    const __nv_bfloat16* __restrict__ Vg = g_v + (size_t)bh * SEQ * HD;
    const unsigned char* __restrict__ maskp = kpm + (size_t)batch * SEQ;

    // Q fragments (q already scaled by 1/8 and rotary in gemm_qkv)
    uint32_t qf[4][4];
    {
        const int r0 = q0 + warp * 16 + (lane >> 2);
        #pragma unroll
        for (int t = 0; t < 4; t++) {
            int c = t * 16 + (lane & 3) * 2;
            qf[t][0] = *(const uint32_t*)&Qg[(size_t)r0 * HD + c];
            qf[t][1] = *(const uint32_t*)&Qg[(size_t)(r0 + 8) * HD + c];
            qf[t][2] = *(const uint32_t*)&Qg[(size_t)r0 * HD + c + 8];
            qf[t][3] = *(const uint32_t*)&Qg[(size_t)(r0 + 8) * HD + c + 8];
        }
    }

    float o[8][4];
    #pragma unroll
    for (int nt = 0; nt < 8; nt++)
        #pragma unroll
        for (int j = 0; j < 4; j++) o[nt][j] = 0.f;
    float mi0 = -INFINITY, mi1 = -INFINITY, li0 = 0.f, li1 = 0.f;

    const int nkb = 2 * qb + 2;

    const int ch0 = tid, ch1 = tid + 256;
    const int lr0 = ch0 >> 3, lc0 = (ch0 & 7) * 8;
    const int lr1 = ch1 >> 3, lc1 = (ch1 & 7) * 8;

    auto issue = [&](int st, int kbase) {
        cpa16(sptr(&Ks[st][lr0][lc0]), Kg + (size_t)(kbase + lr0) * HD + lc0);
        cpa16(sptr(&Ks[st][lr1][lc1]), Kg + (size_t)(kbase + lr1) * HD + lc1);
        cpa16(sptr(&Vs[st][lr0][lc0]), Vg + (size_t)(kbase + lr0) * HD + lc0);
        cpa16(sptr(&Vs[st][lr1][lc1]), Vg + (size_t)(kbase + lr1) * HD + lc1);
        cp_commit();
    };

    issue(0, 0);

    // ldmatrix lane addressing
    const int brow = ((lane >> 4) & 1) * 8 + (lane & 7);  // K (non-trans B)
    const int bhi  = ((lane >> 3) & 1) * 8;
    const int vrow = ((lane >> 3) & 1) * 8 + (lane & 7);  // V (trans B)
    const int vhi  = (lane >> 4) * 8;

    for (int kb = 0; kb < nkb; kb++) {
        const int st = kb & 1;
        const int kbase = kb * 64;
        if (kb + 1 < nkb) issue(st ^ 1, kbase + 64);
        if (kb + 1 < nkb) cp_wait<1>(); else cp_wait<0>();
        __syncthreads();

        const bool active = (kbase <= q0 + warp * 16 + 15);
        if (active) {
            // S = Q K^T
            float s[8][4];
            #pragma unroll
            for (int nt = 0; nt < 8; nt++)
                #pragma unroll
                for (int j = 0; j < 4; j++) s[nt][j] = 0.f;
            #pragma unroll
            for (int ks = 0; ks < 4; ks++) {
                #pragma unroll
                for (int np = 0; np < 4; np++) {
                    uint32_t t0, t1, t2, t3;
                    ldsm4(t0, t1, t2, t3,
                          sptr(&Ks[st][np * 16 + brow][ks * 16 + bhi]));
                    mma16(s[np * 2], qf[ks], t0, t1);
                    mma16(s[np * 2 + 1], qf[ks], t2, t3);
                }
            }

            // masks
            const int row0 = q0 + warp * 16 + (lane >> 2);
            const bool needc = (kbase + 63) > (q0 + warp * 16);
            #pragma unroll
            for (int nt = 0; nt < 8; nt++) {
                int c = nt * 8 + (lane & 3) * 2;
                unsigned char mb0 = maskp[kbase + c], mb1 = maskp[kbase + c + 1];
                if (mb0) { s[nt][0] = -INFINITY; s[nt][2] = -INFINITY; }
                if (mb1) { s[nt][1] = -INFINITY; s[nt][3] = -INFINITY; }
                if (needc) {
                    int cg = kbase + c;
                    if (cg     > row0)     s[nt][0] = -INFINITY;
                    if (cg + 1 > row0)     s[nt][1] = -INFINITY;
                    if (cg     > row0 + 8) s[nt][2] = -INFINITY;
                    if (cg + 1 > row0 + 8) s[nt][3] = -INFINITY;
                }
            }

            // online softmax
            float mx0 = -INFINITY, mx1 = -INFINITY;
            #pragma unroll
            for (int nt = 0; nt < 8; nt++) {
                mx0 = fmaxf(mx0, fmaxf(s[nt][0], s[nt][1]));
                mx1 = fmaxf(mx1, fmaxf(s[nt][2], s[nt][3]));
            }
            mx0 = fmaxf(mx0, __shfl_xor_sync(0xFFFFFFFFu, mx0, 1));
            mx0 = fmaxf(mx0, __shfl_xor_sync(0xFFFFFFFFu, mx0, 2));
            mx1 = fmaxf(mx1, __shfl_xor_sync(0xFFFFFFFFu, mx1, 1));
            mx1 = fmaxf(mx1, __shfl_xor_sync(0xFFFFFFFFu, mx1, 2));
            float mt0 = fmaxf(mi0, mx0), mt1 = fmaxf(mi1, mx1);
            float ms0 = (mt0 == -INFINITY) ? 0.f : mt0;
            float ms1 = (mt1 == -INFINITY) ? 0.f : mt1;
            float al0 = __expf(mi0 - ms0), al1 = __expf(mi1 - ms1);
            mi0 = mt0; mi1 = mt1;
            float rs0 = 0.f, rs1 = 0.f;
            #pragma unroll
            for (int nt = 0; nt < 8; nt++) {
                s[nt][0] = __expf(s[nt][0] - ms0); rs0 += s[nt][0];
                s[nt][1] = __expf(s[nt][1] - ms0); rs0 += s[nt][1];
                s[nt][2] = __expf(s[nt][2] - ms1); rs1 += s[nt][2];
                s[nt][3] = __expf(s[nt][3] - ms1); rs1 += s[nt][3];
            }
            rs0 += __shfl_xor_sync(0xFFFFFFFFu, rs0, 1);
            rs0 += __shfl_xor_sync(0xFFFFFFFFu, rs0, 2);
            rs1 += __shfl_xor_sync(0xFFFFFFFFu, rs1, 1);
            rs1 += __shfl_xor_sync(0xFFFFFFFFu, rs1, 2);
            li0 = li0 * al0 + rs0;
            li1 = li1 * al1 + rs1;
            #pragma unroll
            for (int nt = 0; nt < 8; nt++) {
                o[nt][0] *= al0; o[nt][1] *= al0;
                o[nt][2] *= al1; o[nt][3] *= al1;
            }

            // P accum -> bf16 A-fragments (register-local), O += P V
            #pragma unroll
            for (int t = 0; t < 4; t++) {
                uint32_t pa[4];
                pa[0] = pack_bf16(s[2 * t][0],     s[2 * t][1]);
                pa[1] = pack_bf16(s[2 * t][2],     s[2 * t][3]);
                pa[2] = pack_bf16(s[2 * t + 1][0], s[2 * t + 1][1]);
                pa[3] = pack_bf16(s[2 * t + 1][2], s[2 * t + 1][3]);
                #pragma unroll
                for (int np = 0; np < 4; np++) {
                    uint32_t t0, t1, t2, t3;
                    ldsm4t(t0, t1, t2, t3,
                           sptr(&Vs[st][t * 16 + vrow][np * 16 + vhi]));
                    mma16(o[np * 2], pa, t0, t1);
                    mma16(o[np * 2 + 1], pa, t2, t3);
                }
            }
        }
        __syncthreads();
    }

    // epilogue: normalize + write ctx (bf16)
    const float inv0 = 1.f / li0, inv1 = 1.f / li1;
    const int r0 = q0 + warp * 16 + (lane >> 2);
    #pragma unroll
    for (int nt = 0; nt < 8; nt++) {
        int dc = nt * 8 + (lane & 3) * 2;
        uint32_t w0 = pack_bf16(o[nt][0] * inv0, o[nt][1] * inv0);
        uint32_t w1 = pack_bf16(o[nt][2] * inv1, o[nt][3] * inv1);
        *(uint32_t*)&g_ctx[(size_t)(batch * SEQ + r0) * D_MODEL + h * HD + dc] = w0;
        *(uint32_t*)&g_ctx[(size_t)(batch * SEQ + r0 + 8) * D_MODEL + h * HD + dc] = w1;
    }
}

// ---------------------------------------------------------------------------
extern "C" void kernel_launch(void* const* d_in, const int* in_sizes, int n_in,
                              void* d_out, int out_size) {
    const float* x  = (const float*)d_in[0];
    const unsigned char* kpm = (const unsigned char*)d_in[1];
    const float* qw = (const float*)d_in[2];
    const float* kw = (const float*)d_in[3];
    const float* vw = (const float*)d_in[4];
    const float* ow = (const float*)d_in[5];
    const float* ob = (const float*)d_in[6];
    const float* lg = (const float*)d_in[7];
    const float* lb = (const float*)d_in[8];
    float* out = (float*)d_out;

    const int WN = D_MODEL * D_MODEL / (256 * 4);   // 1024 blocks
    emb_kernel<<<(SEQ * HD + 255) / 256, 256>>>();
    __nv_bfloat16 *wq, *wk, *wv, *wo;
    cudaGetSymbolAddress((void**)&wq, g_wq);
    cudaGetSymbolAddress((void**)&wk, g_wk);
    cudaGetSymbolAddress((void**)&wv, g_wv);
    cudaGetSymbolAddress((void**)&wo, g_wo);
    wcvt_kernel<<<WN, 256>>>(qw, wq);
    wcvt_kernel<<<WN, 256>>>(kw, wk);
    wcvt_kernel<<<WN, 256>>>(vw, wv);
    wcvt_kernel<<<WN, 256>>>(ow, wo);
    ln_kernel<<<MTOT, 256>>>(x, lg, lb);
    gemm_qkv<<<dim3(24, 64), 256>>>();
    attn_kernel<<<dim3(16, 64), 256>>>(kpm);
    gemm_out<<<dim3(8, 64), 256>>>(ob, x, out);
}

// round 5
// speedup vs baseline: 5.4655x; 1.0130x over previous
#include <cuda_runtime.h>
#include <cuda_bf16.h>
#include <cstdint>
#include <math.h>

#define D_MODEL 1024
#define NHEAD   16
#define HD      64
#define SEQ     2048
#define BATCH   4
#define MTOT    (BATCH*SEQ)      // 8192
#define BHN     (BATCH*NHEAD)    // 64

static __device__ __nv_bfloat16 g_xln[MTOT * D_MODEL];
static __device__ __nv_bfloat16 g_q[BHN * SEQ * HD];
static __device__ __nv_bfloat16 g_k[BHN * SEQ * HD];
static __device__ __nv_bfloat16 g_v[BHN * SEQ * HD];
static __device__ __nv_bfloat16 g_ctx[MTOT * D_MODEL];
static __device__ __nv_bfloat16 g_wq[D_MODEL * D_MODEL];
static __device__ __nv_bfloat16 g_wk[D_MODEL * D_MODEL];
static __device__ __nv_bfloat16 g_wv[D_MODEL * D_MODEL];
static __device__ __nv_bfloat16 g_wo[D_MODEL * D_MODEL];
static __device__ float g_emb[SEQ * HD];

// ---------------------------------------------------------------------------
// helpers
// ---------------------------------------------------------------------------
__device__ __forceinline__ uint32_t sptr(const void* p) {
    return (uint32_t)__cvta_generic_to_shared(p);
}
__device__ __forceinline__ uint32_t pack_bf16(float lo, float hi) {
    uint32_t d;
    asm("cvt.rn.bf16x2.f32 %0, %1, %2;" : "=r"(d) : "f"(hi), "f"(lo));
    return d;
}
__device__ __forceinline__ void ldsm4(uint32_t& r0, uint32_t& r1, uint32_t& r2, uint32_t& r3,
                                      uint32_t addr) {
    asm volatile("ldmatrix.sync.aligned.m8n8.x4.shared.b16 {%0,%1,%2,%3}, [%4];"
                 : "=r"(r0), "=r"(r1), "=r"(r2), "=r"(r3) : "r"(addr));
}
__device__ __forceinline__ void ldsm4t(uint32_t& r0, uint32_t& r1, uint32_t& r2, uint32_t& r3,
                                       uint32_t addr) {
    asm volatile("ldmatrix.sync.aligned.m8n8.x4.trans.shared.b16 {%0,%1,%2,%3}, [%4];"
                 : "=r"(r0), "=r"(r1), "=r"(r2), "=r"(r3) : "r"(addr));
}
__device__ __forceinline__ void mma16(float* c, const uint32_t* a, uint32_t b0, uint32_t b1) {
    asm volatile("mma.sync.aligned.m16n8k16.row.col.f32.bf16.bf16.f32 "
                 "{%0,%1,%2,%3}, {%4,%5,%6,%7}, {%8,%9}, {%0,%1,%2,%3};"
                 : "+f"(c[0]), "+f"(c[1]), "+f"(c[2]), "+f"(c[3])
                 : "r"(a[0]), "r"(a[1]), "r"(a[2]), "r"(a[3]), "r"(b0), "r"(b1));
}
__device__ __forceinline__ void cpa16(uint32_t dst, const void* src) {
    asm volatile("cp.async.cg.shared.global [%0], [%1], 16;" :: "r"(dst), "l"(src));
}
__device__ __forceinline__ void cp_commit() { asm volatile("cp.async.commit_group;"); }
template<int N> __device__ __forceinline__ void cp_wait() {
    asm volatile("cp.async.wait_group %0;" :: "n"(N));
}

// ---------------------------------------------------------------------------
__global__ void emb_kernel() {
    int idx = blockIdx.x * blockDim.x + threadIdx.x;
    if (idx >= SEQ * HD) return;
    int s = idx / HD, d = idx % HD;
    int i = d & 31;
    double invf = exp(-((double)(2 * i) / 64.0) * log(10000.0));
    double ang = (double)s * invf;
    g_emb[idx] = (float)((d < 32) ? sin(ang) : cos(ang));
}

// all 4 weight matrices fp32 -> bf16 in one launch: grid (1024, 4)
__global__ __launch_bounds__(256) void wcvt_kernel(const float* __restrict__ qw,
                                                   const float* __restrict__ kw,
                                                   const float* __restrict__ vw,
                                                   const float* __restrict__ ow) {
    const int which = blockIdx.y;
    const float* src = (which == 0) ? qw : (which == 1) ? kw : (which == 2) ? vw : ow;
    __nv_bfloat16* dst = (which == 0) ? g_wq : (which == 1) ? g_wk : (which == 2) ? g_wv : g_wo;
    int i = (blockIdx.x * 256 + threadIdx.x) * 4;
    float4 v = *(const float4*)(src + i);
    uint2 o;
    o.x = pack_bf16(v.x, v.y);
    o.y = pack_bf16(v.z, v.w);
    *(uint2*)(dst + i) = o;
}

// ---------------------------------------------------------------------------
__global__ __launch_bounds__(256) void ln_kernel(const float* __restrict__ x,
                                                 const float* __restrict__ gam,
                                                 const float* __restrict__ bet) {
    int row = blockIdx.x;
    const float4* xr = (const float4*)(x + (size_t)row * D_MODEL);
    float4 v = xr[threadIdx.x];
    float sum = v.x + v.y + v.z + v.w;
    float sq  = v.x*v.x + v.y*v.y + v.z*v.z + v.w*v.w;
    #pragma unroll
    for (int o = 16; o; o >>= 1) {
        sum += __shfl_xor_sync(0xFFFFFFFFu, sum, o);
        sq  += __shfl_xor_sync(0xFFFFFFFFu, sq, o);
    }
    __shared__ float ssum[8], ssq[8];
    int w = threadIdx.x >> 5, l = threadIdx.x & 31;
    if (!l) { ssum[w] = sum; ssq[w] = sq; }
    __syncthreads();
    if (w == 0) {
        sum = (l < 8) ? ssum[l] : 0.f;
        sq  = (l < 8) ? ssq[l]  : 0.f;
        #pragma unroll
        for (int o = 4; o; o >>= 1) {
            sum += __shfl_xor_sync(0xFFFFFFFFu, sum, o);
            sq  += __shfl_xor_sync(0xFFFFFFFFu, sq, o);
        }
        if (!l) { ssum[0] = sum; ssq[0] = sq; }
    }
    __syncthreads();
    float mu  = ssum[0] * (1.f / D_MODEL);
    float var = ssq[0] * (1.f / D_MODEL) - mu * mu;
    float rs  = rsqrtf(var + 1e-5f);
    int c = threadIdx.x * 4;
    float4 g4 = *(const float4*)(gam + c);
    float4 b4 = *(const float4*)(bet + c);
    uint2 o;
    o.x = pack_bf16((v.x - mu) * rs * g4.x + b4.x, (v.y - mu) * rs * g4.y + b4.y);
    o.y = pack_bf16((v.z - mu) * rs * g4.z + b4.z, (v.w - mu) * rs * g4.w + b4.w);
    *(uint2*)(g_xln + (size_t)row * D_MODEL + c) = o;
}

// ---------------------------------------------------------------------------
// bf16 GEMM core: CTA 128x128, k-stage 32, double-buffered cp.async.
// 8 warps (2m x 4n), warp 64x32, mma m16n8k16.
// ---------------------------------------------------------------------------
struct GemmAcc { float a[4][4][4]; };

__device__ __forceinline__ void gemm_core(const __nv_bfloat16* __restrict__ A,
                                          const __nv_bfloat16* __restrict__ B,
                                          int m0, int n0, GemmAcc& G) {
    __shared__ __align__(16) __nv_bfloat16 Asb[2][128][40];
    __shared__ __align__(16) __nv_bfloat16 Bsb[2][128][40];

    const int tid  = threadIdx.x;
    const int lane = tid & 31, warp = tid >> 5;
    const int wm = warp >> 2, wn = warp & 3;

    #pragma unroll
    for (int mt = 0; mt < 4; mt++)
        #pragma unroll
        for (int nt = 0; nt < 4; nt++)
            #pragma unroll
            for (int j = 0; j < 4; j++) G.a[mt][nt][j] = 0.f;

    const int c0 = tid, c1 = tid + 256;
    const int r0c = c0 >> 2, k0c = (c0 & 3) * 8;
    const int r1c = c1 >> 2, k1c = (c1 & 3) * 8;

    auto issue = [&](int st, int k0) {
        cpa16(sptr(&Asb[st][r0c][k0c]), A + (size_t)(m0 + r0c) * D_MODEL + k0 + k0c);
        cpa16(sptr(&Asb[st][r1c][k1c]), A + (size_t)(m0 + r1c) * D_MODEL + k0 + k1c);
        cpa16(sptr(&Bsb[st][r0c][k0c]), B + (size_t)(n0 + r0c) * D_MODEL + k0 + k0c);
        cpa16(sptr(&Bsb[st][r1c][k1c]), B + (size_t)(n0 + r1c) * D_MODEL + k0 + k1c);
        cp_commit();
    };

    issue(0, 0);

    // ldmatrix lane addressing
    const int arow = (lane & 15);
    const int ahi  = (lane >> 4) * 8;          // A k-offset
    const int brow = ((lane >> 4) & 1) * 8 + (lane & 7);
    const int bhi  = ((lane >> 3) & 1) * 8;    // B k-offset

    for (int kt = 0; kt < 32; kt++) {
        const int st = kt & 1;
        if (kt + 1 < 32) issue(st ^ 1, (kt + 1) * 32);
        if (kt + 1 < 32) cp_wait<1>(); else cp_wait<0>();
        __syncthreads();

        #pragma unroll
        for (int ks = 0; ks < 2; ks++) {
            const int kk = ks * 16;
            uint32_t af[4][4];
            #pragma unroll
            for (int mt = 0; mt < 4; mt++)
                ldsm4(af[mt][0], af[mt][1], af[mt][2], af[mt][3],
                      sptr(&Asb[st][wm * 64 + mt * 16 + arow][kk + ahi]));
            uint32_t bf[4][2];
            #pragma unroll
            for (int np = 0; np < 2; np++) {
                uint32_t t0, t1, t2, t3;
                ldsm4(t0, t1, t2, t3,
                      sptr(&Bsb[st][wn * 32 + np * 16 + brow][kk + bhi]));
                bf[np * 2][0] = t0;     bf[np * 2][1] = t1;
                bf[np * 2 + 1][0] = t2; bf[np * 2 + 1][1] = t3;
            }
            #pragma unroll
            for (int mt = 0; mt < 4; mt++)
                #pragma unroll
                for (int nt = 0; nt < 4; nt++)
                    mma16(G.a[mt][nt], af[mt], bf[nt][0], bf[nt][1]);
        }
        __syncthreads();
    }
}

// ---------------------------------------------------------------------------
// QKV proj: grid (24, 64). Fused rotary (+0.125 scale on q) + head-split.
// ---------------------------------------------------------------------------
__global__ __launch_bounds__(256, 2) void gemm_qkv() {
    const int m0 = blockIdx.y * 128;
    const int which = blockIdx.x >> 3;
    const int n0 = (blockIdx.x & 7) * 128;
    const __nv_bfloat16* W = (which == 0) ? g_wq : (which == 1) ? g_wk : g_wv;

    GemmAcc G;
    gemm_core(g_xln, W, m0, n0, G);

    const int lane = threadIdx.x & 31, warp = threadIdx.x >> 5;
    const int wm = warp >> 2, wn = warp & 3;
    __nv_bfloat16* dst = (which == 0) ? g_q : (which == 1) ? g_k : g_v;

    #pragma unroll
    for (int mt = 0; mt < 4; mt++) {
        #pragma unroll
        for (int rh = 0; rh < 2; rh++) {
            int m = m0 + wm * 64 + mt * 16 + rh * 8 + (lane >> 2);
            int b = m >> 11, s = m & 2047;
            #pragma unroll
            for (int nt = 0; nt < 4; nt++) {
                int n  = n0 + wn * 32 + nt * 8 + (lane & 3) * 2;
                int h  = n >> 6, dc = n & 63;
                float ex = 1.f, ey = 1.f;
                if (which < 2) {
                    float2 e = *(const float2*)&g_emb[s * HD + dc];
                    ex = e.x; ey = e.y;
                    if (which == 0) { ex *= 0.125f; ey *= 0.125f; }
                }
                uint32_t o = pack_bf16(G.a[mt][nt][rh * 2 + 0] * ex,
                                       G.a[mt][nt][rh * 2 + 1] * ey);
                *(uint32_t*)&dst[((size_t)(b * NHEAD + h) * SEQ + s) * HD + dc] = o;
            }
        }
    }
}

// ---------------------------------------------------------------------------
// out proj + bias + residual: grid (8, 64)
// ---------------------------------------------------------------------------
__global__ __launch_bounds__(256, 2) void gemm_out(const float* __restrict__ ob,
                                                   const float* __restrict__ x,
                                                   float* __restrict__ out) {
    const int m0 = blockIdx.y * 128;
    const int n0 = blockIdx.x * 128;

    GemmAcc G;
    gemm_core(g_ctx, g_wo, m0, n0, G);

    const int lane = threadIdx.x & 31, warp = threadIdx.x >> 5;
    const int wm = warp >> 2, wn = warp & 3;

    #pragma unroll
    for (int mt = 0; mt < 4; mt++) {
        #pragma unroll
        for (int rh = 0; rh < 2; rh++) {
            int m = m0 + wm * 64 + mt * 16 + rh * 8 + (lane >> 2);
            #pragma unroll
            for (int nt = 0; nt < 4; nt++) {
                int n = n0 + wn * 32 + nt * 8 + (lane & 3) * 2;
                float2 bb = *(const float2*)&ob[n];
                float2 xx = *(const float2*)&x[(size_t)m * D_MODEL + n];
                float2 o;
                o.x = G.a[mt][nt][rh * 2 + 0] + bb.x + xx.x;
                o.y = G.a[mt][nt][rh * 2 + 1] + bb.y + xx.y;
                *(float2*)&out[(size_t)m * D_MODEL + n] = o;
            }
        }
    }
}

// ---------------------------------------------------------------------------
// Flash attention, bf16 mma. grid (8, 64). Each CTA handles TWO q-tiles
// (qb = bx and qb = 15-bx) for uniform work: 34 k-block iterations per CTA.
// ---------------------------------------------------------------------------
__global__ __launch_bounds__(256, 2) void attn_kernel(const unsigned char* __restrict__ kpm) {
    __shared__ __align__(16) __nv_bfloat16 Ks[2][64][72];
    __shared__ __align__(16) __nv_bfloat16 Vs[2][64][72];

    const int tid = threadIdx.x, lane = tid & 31, warp = tid >> 5;
    const int bh = blockIdx.y;
    const int batch = bh >> 4, h = bh & 15;

    const __nv_bfloat16* __restrict__ Qg = g_q + (size_t)bh * SEQ * HD;
    const __nv_bfloat16* __restrict__ Kg = g_k + (size_t)bh * SEQ * HD;
    const __nv_bfloat16* __restrict__ Vg = g_v + (size_t)bh * SEQ * HD;
    const unsigned char* __restrict__ maskp = kpm + (size_t)batch * SEQ;

    const int ch0 = tid, ch1 = tid + 256;
    const int lr0 = ch0 >> 3, lc0 = (ch0 & 7) * 8;
    const int lr1 = ch1 >> 3, lc1 = (ch1 & 7) * 8;

    auto issue = [&](int st, int kbase) {
        cpa16(sptr(&Ks[st][lr0][lc0]), Kg + (size_t)(kbase + lr0) * HD + lc0);
        cpa16(sptr(&Ks[st][lr1][lc1]), Kg + (size_t)(kbase + lr1) * HD + lc1);
        cpa16(sptr(&Vs[st][lr0][lc0]), Vg + (size_t)(kbase + lr0) * HD + lc0);
        cpa16(sptr(&Vs[st][lr1][lc1]), Vg + (size_t)(kbase + lr1) * HD + lc1);
        cp_commit();
    };

    // ldmatrix lane addressing
    const int brow = ((lane >> 4) & 1) * 8 + (lane & 7);  // K (non-trans B)
    const int bhi  = ((lane >> 3) & 1) * 8;
    const int vrow = ((lane >> 3) & 1) * 8 + (lane & 7);  // V (trans B)
    const int vhi  = (lane >> 4) * 8;

    #pragma unroll 1
    for (int ph = 0; ph < 2; ph++) {
        const int qb = ph ? (15 - blockIdx.x) : blockIdx.x;
        const int q0 = qb * 128;
        const int nkb = 2 * qb + 2;

        // Q fragments (q already scaled by 1/8 and rotary in gemm_qkv)
        uint32_t qf[4][4];
        {
            const int r0 = q0 + warp * 16 + (lane >> 2);
            #pragma unroll
            for (int t = 0; t < 4; t++) {
                int c = t * 16 + (lane & 3) * 2;
                qf[t][0] = *(const uint32_t*)&Qg[(size_t)r0 * HD + c];
                qf[t][1] = *(const uint32_t*)&Qg[(size_t)(r0 + 8) * HD + c];
                qf[t][2] = *(const uint32_t*)&Qg[(size_t)r0 * HD + c + 8];
                qf[t][3] = *(const uint32_t*)&Qg[(size_t)(r0 + 8) * HD + c + 8];
            }
        }

        float o[8][4];
        #pragma unroll
        for (int nt = 0; nt < 8; nt++)
            #pragma unroll
            for (int j = 0; j < 4; j++) o[nt][j] = 0.f;
        float mi0 = -INFINITY, mi1 = -INFINITY, li0 = 0.f, li1 = 0.f;

        issue(0, 0);

        #pragma unroll 1
        for (int kb = 0; kb < nkb; kb++) {
            const int st = kb & 1;
            const int kbase = kb * 64;
            if (kb + 1 < nkb) issue(st ^ 1, kbase + 64);
            if (kb + 1 < nkb) cp_wait<1>(); else cp_wait<0>();
            __syncthreads();

            const bool active = (kbase <= q0 + warp * 16 + 15);
            if (active) {
                // S = Q K^T
                float s[8][4];
                #pragma unroll
                for (int nt = 0; nt < 8; nt++)
                    #pragma unroll
                    for (int j = 0; j < 4; j++) s[nt][j] = 0.f;
                #pragma unroll
                for (int ks = 0; ks < 4; ks++) {
                    #pragma unroll
                    for (int np = 0; np < 4; np++) {
                        uint32_t t0, t1, t2, t3;
                        ldsm4(t0, t1, t2, t3,
                              sptr(&Ks[st][np * 16 + brow][ks * 16 + bhi]));
                        mma16(s[np * 2], qf[ks], t0, t1);
                        mma16(s[np * 2 + 1], qf[ks], t2, t3);
                    }
                }

                // masks
                const int row0 = q0 + warp * 16 + (lane >> 2);
                const bool needc = (kbase + 63) > (q0 + warp * 16);
                #pragma unroll
                for (int nt = 0; nt < 8; nt++) {
                    int c = nt * 8 + (lane & 3) * 2;
                    unsigned char mb0 = maskp[kbase + c], mb1 = maskp[kbase + c + 1];
                    if (mb0) { s[nt][0] = -INFINITY; s[nt][2] = -INFINITY; }
                    if (mb1) { s[nt][1] = -INFINITY; s[nt][3] = -INFINITY; }
                    if (needc) {
                        int cg = kbase + c;
                        if (cg     > row0)     s[nt][0] = -INFINITY;
                        if (cg + 1 > row0)     s[nt][1] = -INFINITY;
                        if (cg     > row0 + 8) s[nt][2] = -INFINITY;
                        if (cg + 1 > row0 + 8) s[nt][3] = -INFINITY;
                    }
                }

                // online softmax
                float mx0 = -INFINITY, mx1 = -INFINITY;
                #pragma unroll
                for (int nt = 0; nt < 8; nt++) {
                    mx0 = fmaxf(mx0, fmaxf(s[nt][0], s[nt][1]));
                    mx1 = fmaxf(mx1, fmaxf(s[nt][2], s[nt][3]));
                }
                mx0 = fmaxf(mx0, __shfl_xor_sync(0xFFFFFFFFu, mx0, 1));
                mx0 = fmaxf(mx0, __shfl_xor_sync(0xFFFFFFFFu, mx0, 2));
                mx1 = fmaxf(mx1, __shfl_xor_sync(0xFFFFFFFFu, mx1, 1));
                mx1 = fmaxf(mx1, __shfl_xor_sync(0xFFFFFFFFu, mx1, 2));
                float mt0 = fmaxf(mi0, mx0), mt1 = fmaxf(mi1, mx1);
                float ms0 = (mt0 == -INFINITY) ? 0.f : mt0;
                float ms1 = (mt1 == -INFINITY) ? 0.f : mt1;
                float al0 = __expf(mi0 - ms0), al1 = __expf(mi1 - ms1);
                mi0 = mt0; mi1 = mt1;
                float rs0 = 0.f, rs1 = 0.f;
                #pragma unroll
                for (int nt = 0; nt < 8; nt++) {
                    s[nt][0] = __expf(s[nt][0] - ms0); rs0 += s[nt][0];
                    s[nt][1] = __expf(s[nt][1] - ms0); rs0 += s[nt][1];
                    s[nt][2] = __expf(s[nt][2] - ms1); rs1 += s[nt][2];
                    s[nt][3] = __expf(s[nt][3] - ms1); rs1 += s[nt][3];
                }
                rs0 += __shfl_xor_sync(0xFFFFFFFFu, rs0, 1);
                rs0 += __shfl_xor_sync(0xFFFFFFFFu, rs0, 2);
                rs1 += __shfl_xor_sync(0xFFFFFFFFu, rs1, 1);
                rs1 += __shfl_xor_sync(0xFFFFFFFFu, rs1, 2);
                li0 = li0 * al0 + rs0;
                li1 = li1 * al1 + rs1;
                #pragma unroll
                for (int nt = 0; nt < 8; nt++) {
                    o[nt][0] *= al0; o[nt][1] *= al0;
                    o[nt][2] *= al1; o[nt][3] *= al1;
                }

                // P accum -> bf16 A-fragments (register-local), O += P V
                #pragma unroll
                for (int t = 0; t < 4; t++) {
                    uint32_t pa[4];
                    pa[0] = pack_bf16(s[2 * t][0],     s[2 * t][1]);
                    pa[1] = pack_bf16(s[2 * t][2],     s[2 * t][3]);
                    pa[2] = pack_bf16(s[2 * t + 1][0], s[2 * t + 1][1]);
                    pa[3] = pack_bf16(s[2 * t + 1][2], s[2 * t + 1][3]);
                    #pragma unroll
                    for (int np = 0; np < 4; np++) {
                        uint32_t t0, t1, t2, t3;
                        ldsm4t(t0, t1, t2, t3,
                               sptr(&Vs[st][t * 16 + vrow][np * 16 + vhi]));
                        mma16(o[np * 2], pa, t0, t1);
                        mma16(o[np * 2 + 1], pa, t2, t3);
                    }
                }
            }
            __syncthreads();
        }

        // epilogue: normalize + write ctx (bf16)
        const float inv0 = 1.f / li0, inv1 = 1.f / li1;
        const int r0 = q0 + warp * 16 + (lane >> 2);
        #pragma unroll
        for (int nt = 0; nt < 8; nt++) {
            int dc = nt * 8 + (lane & 3) * 2;
            uint32_t w0 = pack_bf16(o[nt][0] * inv0, o[nt][1] * inv0);
            uint32_t w1 = pack_bf16(o[nt][2] * inv1, o[nt][3] * inv1);
            *(uint32_t*)&g_ctx[(size_t)(batch * SEQ + r0) * D_MODEL + h * HD + dc] = w0;
            *(uint32_t*)&g_ctx[(size_t)(batch * SEQ + r0 + 8) * D_MODEL + h * HD + dc] = w1;
        }
    }
}

// ---------------------------------------------------------------------------
extern "C" void kernel_launch(void* const* d_in, const int* in_sizes, int n_in,
                              void* d_out, int out_size) {
    const float* x  = (const float*)d_in[0];
    const unsigned char* kpm = (const unsigned char*)d_in[1];
    const float* qw = (const float*)d_in[2];
    const float* kw = (const float*)d_in[3];
    const float* vw = (const float*)d_in[4];
    const float* ow = (const float*)d_in[5];
    const float* ob = (const float*)d_in[6];
    const float* lg = (const float*)d_in[7];
    const float* lb = (const float*)d_in[8];
    float* out = (float*)d_out;

    emb_kernel<<<(SEQ * HD + 255) / 256, 256>>>();
    wcvt_kernel<<<dim3(D_MODEL * D_MODEL / (256 * 4), 4), 256>>>(qw, kw, vw, ow);
    ln_kernel<<<MTOT, 256>>>(x, lg, lb);
    gemm_qkv<<<dim3(24, 64), 256>>>();
    attn_kernel<<<dim3(8, 64), 256>>>(kpm);
    gemm_out<<<dim3(8, 64), 256>>>(ob, x, out);
}

// round 6
// speedup vs baseline: 5.6322x; 1.0305x over previous
#include <cuda_runtime.h>
#include <cuda_bf16.h>
#include <cstdint>
#include <math.h>

#define D_MODEL 1024
#define NHEAD   16
#define HD      64
#define SEQ     2048
#define BATCH   4
#define MTOT    (BATCH*SEQ)      // 8192
#define BHN     (BATCH*NHEAD)    // 64

static __device__ __nv_bfloat16 g_xln[MTOT * D_MODEL];
static __device__ __nv_bfloat16 g_q[BHN * SEQ * HD];
static __device__ __nv_bfloat16 g_k[BHN * SEQ * HD];
static __device__ __nv_bfloat16 g_v[BHN * SEQ * HD];
static __device__ __nv_bfloat16 g_ctx[MTOT * D_MODEL];
static __device__ __nv_bfloat16 g_wq[D_MODEL * D_MODEL];
static __device__ __nv_bfloat16 g_wk[D_MODEL * D_MODEL];
static __device__ __nv_bfloat16 g_wv[D_MODEL * D_MODEL];
static __device__ __nv_bfloat16 g_wo[D_MODEL * D_MODEL];
static __device__ float g_emb[SEQ * HD];

// GEMM smem: 3 stages x (A[128][40] + B[128][40]) bf16
#define G_STAGE_BYTES 20480
#define G_SMEM_BYTES  (3 * G_STAGE_BYTES)
// attn smem: 3 stages x (K[64][72] + V[64][72]) bf16
#define A_STAGE_BYTES 18432
#define A_SMEM_BYTES  (3 * A_STAGE_BYTES)

// ---------------------------------------------------------------------------
// helpers
// ---------------------------------------------------------------------------
__device__ __forceinline__ uint32_t sptr(const void* p) {
    return (uint32_t)__cvta_generic_to_shared(p);
}
__device__ __forceinline__ uint32_t pack_bf16(float lo, float hi) {
    uint32_t d;
    asm("cvt.rn.bf16x2.f32 %0, %1, %2;" : "=r"(d) : "f"(hi), "f"(lo));
    return d;
}
__device__ __forceinline__ void ldsm4(uint32_t& r0, uint32_t& r1, uint32_t& r2, uint32_t& r3,
                                      uint32_t addr) {
    asm volatile("ldmatrix.sync.aligned.m8n8.x4.shared.b16 {%0,%1,%2,%3}, [%4];"
                 : "=r"(r0), "=r"(r1), "=r"(r2), "=r"(r3) : "r"(addr));
}
__device__ __forceinline__ void ldsm4t(uint32_t& r0, uint32_t& r1, uint32_t& r2, uint32_t& r3,
                                       uint32_t addr) {
    asm volatile("ldmatrix.sync.aligned.m8n8.x4.trans.shared.b16 {%0,%1,%2,%3}, [%4];"
                 : "=r"(r0), "=r"(r1), "=r"(r2), "=r"(r3) : "r"(addr));
}
__device__ __forceinline__ void mma16(float* c, const uint32_t* a, uint32_t b0, uint32_t b1) {
    asm volatile("mma.sync.aligned.m16n8k16.row.col.f32.bf16.bf16.f32 "
                 "{%0,%1,%2,%3}, {%4,%5,%6,%7}, {%8,%9}, {%0,%1,%2,%3};"
                 : "+f"(c[0]), "+f"(c[1]), "+f"(c[2]), "+f"(c[3])
                 : "r"(a[0]), "r"(a[1]), "r"(a[2]), "r"(a[3]), "r"(b0), "r"(b1));
}
__device__ __forceinline__ void cpa16(uint32_t dst, const void* src) {
    asm volatile("cp.async.cg.shared.global [%0], [%1], 16;" :: "r"(dst), "l"(src));
}
__device__ __forceinline__ void cp_commit() { asm volatile("cp.async.commit_group;"); }
template<int N> __device__ __forceinline__ void cp_wait() {
    asm volatile("cp.async.wait_group %0;" :: "n"(N));
}

// ---------------------------------------------------------------------------
__global__ void emb_kernel() {
    int idx = blockIdx.x * blockDim.x + threadIdx.x;
    if (idx >= SEQ * HD) return;
    int s = idx / HD, d = idx % HD;
    int i = d & 31;
    double invf = exp(-((double)(2 * i) / 64.0) * log(10000.0));
    double ang = (double)s * invf;
    g_emb[idx] = (float)((d < 32) ? sin(ang) : cos(ang));
}

// all 4 weight matrices fp32 -> bf16 in one launch: grid (1024, 4)
__global__ __launch_bounds__(256) void wcvt_kernel(const float* __restrict__ qw,
                                                   const float* __restrict__ kw,
                                                   const float* __restrict__ vw,
                                                   const float* __restrict__ ow) {
    const int which = blockIdx.y;
    const float* src = (which == 0) ? qw : (which == 1) ? kw : (which == 2) ? vw : ow;
    __nv_bfloat16* dst = (which == 0) ? g_wq : (which == 1) ? g_wk : (which == 2) ? g_wv : g_wo;
    int i = (blockIdx.x * 256 + threadIdx.x) * 4;
    float4 v = *(const float4*)(src + i);
    uint2 o;
    o.x = pack_bf16(v.x, v.y);
    o.y = pack_bf16(v.z, v.w);
    *(uint2*)(dst + i) = o;
}

// ---------------------------------------------------------------------------
__global__ __launch_bounds__(256) void ln_kernel(const float* __restrict__ x,
                                                 const float* __restrict__ gam,
                                                 const float* __restrict__ bet) {
    int row = blockIdx.x;
    const float4* xr = (const float4*)(x + (size_t)row * D_MODEL);
    float4 v = xr[threadIdx.x];
    float sum = v.x + v.y + v.z + v.w;
    float sq  = v.x*v.x + v.y*v.y + v.z*v.z + v.w*v.w;
    #pragma unroll
    for (int o = 16; o; o >>= 1) {
        sum += __shfl_xor_sync(0xFFFFFFFFu, sum, o);
        sq  += __shfl_xor_sync(0xFFFFFFFFu, sq, o);
    }
    __shared__ float ssum[8], ssq[8];
    int w = threadIdx.x >> 5, l = threadIdx.x & 31;
    if (!l) { ssum[w] = sum; ssq[w] = sq; }
    __syncthreads();
    if (w == 0) {
        sum = (l < 8) ? ssum[l] : 0.f;
        sq  = (l < 8) ? ssq[l]  : 0.f;
        #pragma unroll
        for (int o = 4; o; o >>= 1) {
            sum += __shfl_xor_sync(0xFFFFFFFFu, sum, o);
            sq  += __shfl_xor_sync(0xFFFFFFFFu, sq, o);
        }
        if (!l) { ssum[0] = sum; ssq[0] = sq; }
    }
    __syncthreads();
    float mu  = ssum[0] * (1.f / D_MODEL);
    float var = ssq[0] * (1.f / D_MODEL) - mu * mu;
    float rs  = rsqrtf(var + 1e-5f);
    int c = threadIdx.x * 4;
    float4 g4 = *(const float4*)(gam + c);
    float4 b4 = *(const float4*)(bet + c);
    uint2 o;
    o.x = pack_bf16((v.x - mu) * rs * g4.x + b4.x, (v.y - mu) * rs * g4.y + b4.y);
    o.y = pack_bf16((v.z - mu) * rs * g4.z + b4.z, (v.w - mu) * rs * g4.w + b4.w);
    *(uint2*)(g_xln + (size_t)row * D_MODEL + c) = o;
}

// ---------------------------------------------------------------------------
// bf16 GEMM core: CTA 128x128, k-stage 32, 3-stage cp.async ring,
// ONE __syncthreads per k-iteration. 8 warps (2m x 4n), mma m16n8k16.
// ---------------------------------------------------------------------------
struct GemmAcc { float a[4][4][4]; };

__device__ __forceinline__ void gemm_core(const __nv_bfloat16* __restrict__ A,
                                          const __nv_bfloat16* __restrict__ B,
                                          int m0, int n0, GemmAcc& G, char* sm) {
    const int tid  = threadIdx.x;
    const int lane = tid & 31, warp = tid >> 5;
    const int wm = warp >> 2, wn = warp & 3;

    #pragma unroll
    for (int mt = 0; mt < 4; mt++)
        #pragma unroll
        for (int nt = 0; nt < 4; nt++)
            #pragma unroll
            for (int j = 0; j < 4; j++) G.a[mt][nt][j] = 0.f;

    const int c0 = tid, c1 = tid + 256;
    const int r0c = c0 >> 2, k0c = (c0 & 3) * 8;
    const int r1c = c1 >> 2, k1c = (c1 & 3) * 8;

    auto stageA = [&](int st) { return (__nv_bfloat16*)(sm + st * G_STAGE_BYTES); };
    auto stageB = [&](int st) { return (__nv_bfloat16*)(sm + st * G_STAGE_BYTES + 10240); };

    auto issue = [&](int st, int k0) {
        __nv_bfloat16* As = stageA(st);
        __nv_bfloat16* Bs = stageB(st);
        cpa16(sptr(As + r0c * 40 + k0c), A + (size_t)(m0 + r0c) * D_MODEL + k0 + k0c);
        cpa16(sptr(As + r1c * 40 + k1c), A + (size_t)(m0 + r1c) * D_MODEL + k0 + k1c);
        cpa16(sptr(Bs + r0c * 40 + k0c), B + (size_t)(n0 + r0c) * D_MODEL + k0 + k0c);
        cpa16(sptr(Bs + r1c * 40 + k1c), B + (size_t)(n0 + r1c) * D_MODEL + k0 + k1c);
        cp_commit();
    };

    issue(0, 0);
    issue(1, 32);

    // ldmatrix lane addressing
    const int arow = (lane & 15);
    const int ahi  = (lane >> 4) * 8;
    const int brow = ((lane >> 4) & 1) * 8 + (lane & 7);
    const int bhi  = ((lane >> 3) & 1) * 8;

    for (int kt = 0; kt < 32; kt++) {
        const int st = kt - (kt / 3) * 3;
        if (kt < 31) cp_wait<1>(); else cp_wait<0>();
        __syncthreads();
        if (kt + 2 < 32) issue((kt + 2) - ((kt + 2) / 3) * 3, (kt + 2) * 32);

        __nv_bfloat16* As = stageA(st);
        __nv_bfloat16* Bs = stageB(st);
        #pragma unroll
        for (int ks = 0; ks < 2; ks++) {
            const int kk = ks * 16;
            uint32_t af[4][4];
            #pragma unroll
            for (int mt = 0; mt < 4; mt++)
                ldsm4(af[mt][0], af[mt][1], af[mt][2], af[mt][3],
                      sptr(As + (wm * 64 + mt * 16 + arow) * 40 + kk + ahi));
            uint32_t bf[4][2];
            #pragma unroll
            for (int np = 0; np < 2; np++) {
                uint32_t t0, t1, t2, t3;
                ldsm4(t0, t1, t2, t3,
                      sptr(Bs + (wn * 32 + np * 16 + brow) * 40 + kk + bhi));
                bf[np * 2][0] = t0;     bf[np * 2][1] = t1;
                bf[np * 2 + 1][0] = t2; bf[np * 2 + 1][1] = t3;
            }
            #pragma unroll
            for (int mt = 0; mt < 4; mt++)
                #pragma unroll
                for (int nt = 0; nt < 4; nt++)
                    mma16(G.a[mt][nt], af[mt], bf[nt][0], bf[nt][1]);
        }
    }
}

// ---------------------------------------------------------------------------
// QKV proj: grid (24, 64). Fused rotary (+0.125 scale on q) + head-split.
// ---------------------------------------------------------------------------
__global__ __launch_bounds__(256, 2) void gemm_qkv() {
    extern __shared__ char dynsm_g[];
    const int m0 = blockIdx.y * 128;
    const int which = blockIdx.x >> 3;
    const int n0 = (blockIdx.x & 7) * 128;
    const __nv_bfloat16* W = (which == 0) ? g_wq : (which == 1) ? g_wk : g_wv;

    GemmAcc G;
    gemm_core(g_xln, W, m0, n0, G, dynsm_g);

    const int lane = threadIdx.x & 31, warp = threadIdx.x >> 5;
    const int wm = warp >> 2, wn = warp & 3;
    __nv_bfloat16* dst = (which == 0) ? g_q : (which == 1) ? g_k : g_v;

    #pragma unroll
    for (int mt = 0; mt < 4; mt++) {
        #pragma unroll
        for (int rh = 0; rh < 2; rh++) {
            int m = m0 + wm * 64 + mt * 16 + rh * 8 + (lane >> 2);
            int b = m >> 11, s = m & 2047;
            #pragma unroll
            for (int nt = 0; nt < 4; nt++) {
                int n  = n0 + wn * 32 + nt * 8 + (lane & 3) * 2;
                int h  = n >> 6, dc = n & 63;
                float ex = 1.f, ey = 1.f;
                if (which < 2) {
                    float2 e = *(const float2*)&g_emb[s * HD + dc];
                    ex = e.x; ey = e.y;
                    if (which == 0) { ex *= 0.125f; ey *= 0.125f; }
                }
                uint32_t o = pack_bf16(G.a[mt][nt][rh * 2 + 0] * ex,
                                       G.a[mt][nt][rh * 2 + 1] * ey);
                *(uint32_t*)&dst[((size_t)(b * NHEAD + h) * SEQ + s) * HD + dc] = o;
            }
        }
    }
}

// ---------------------------------------------------------------------------
// out proj + bias + residual: grid (8, 64)
// ---------------------------------------------------------------------------
__global__ __launch_bounds__(256, 2) void gemm_out(const float* __restrict__ ob,
                                                   const float* __restrict__ x,
                                                   float* __restrict__ out) {
    extern __shared__ char dynsm_o[];
    const int m0 = blockIdx.y * 128;
    const int n0 = blockIdx.x * 128;

    GemmAcc G;
    gemm_core(g_ctx, g_wo, m0, n0, G, dynsm_o);

    const int lane = threadIdx.x & 31, warp = threadIdx.x >> 5;
    const int wm = warp >> 2, wn = warp & 3;

    #pragma unroll
    for (int mt = 0; mt < 4; mt++) {
        #pragma unroll
        for (int rh = 0; rh < 2; rh++) {
            int m = m0 + wm * 64 + mt * 16 + rh * 8 + (lane >> 2);
            #pragma unroll
            for (int nt = 0; nt < 4; nt++) {
                int n = n0 + wn * 32 + nt * 8 + (lane & 3) * 2;
                float2 bb = *(const float2*)&ob[n];
                float2 xx = *(const float2*)&x[(size_t)m * D_MODEL + n];
                float2 o;
                o.x = G.a[mt][nt][rh * 2 + 0] + bb.x + xx.x;
                o.y = G.a[mt][nt][rh * 2 + 1] + bb.y + xx.y;
                *(float2*)&out[(size_t)m * D_MODEL + n] = o;
            }
        }
    }
}

// ---------------------------------------------------------------------------
// Flash attention, bf16 mma. grid (8, 64). Two q-tiles per CTA
// (qb = bx and 15-bx). 3-stage K/V ring, one __syncthreads per k-block.
// ---------------------------------------------------------------------------
__global__ __launch_bounds__(256, 2) void attn_kernel(const unsigned char* __restrict__ kpm) {
    extern __shared__ char dynsm_a[];

    const int tid = threadIdx.x, lane = tid & 31, warp = tid >> 5;
    const int bh = blockIdx.y;
    const int batch = bh >> 4, h = bh & 15;

    const __nv_bfloat16* __restrict__ Qg = g_q + (size_t)bh * SEQ * HD;
    const __nv_bfloat16* __restrict__ Kg = g_k + (size_t)bh * SEQ * HD;
    const __nv_bfloat16* __restrict__ Vg = g_v + (size_t)bh * SEQ * HD;
    const unsigned char* __restrict__ maskp = kpm + (size_t)batch * SEQ;

    const int ch0 = tid, ch1 = tid + 256;
    const int lr0 = ch0 >> 3, lc0 = (ch0 & 7) * 8;
    const int lr1 = ch1 >> 3, lc1 = (ch1 & 7) * 8;

    auto stageK = [&](int st) { return (__nv_bfloat16*)(dynsm_a + st * A_STAGE_BYTES); };
    auto stageV = [&](int st) { return (__nv_bfloat16*)(dynsm_a + st * A_STAGE_BYTES + 9216); };

    auto issue = [&](int st, int kbase) {
        __nv_bfloat16* Ks = stageK(st);
        __nv_bfloat16* Vs = stageV(st);
        cpa16(sptr(Ks + lr0 * 72 + lc0), Kg + (size_t)(kbase + lr0) * HD + lc0);
        cpa16(sptr(Ks + lr1 * 72 + lc1), Kg + (size_t)(kbase + lr1) * HD + lc1);
        cpa16(sptr(Vs + lr0 * 72 + lc0), Vg + (size_t)(kbase + lr0) * HD + lc0);
        cpa16(sptr(Vs + lr1 * 72 + lc1), Vg + (size_t)(kbase + lr1) * HD + lc1);
        cp_commit();
    };

    // ldmatrix lane addressing
    const int brow = ((lane >> 4) & 1) * 8 + (lane & 7);  // K (non-trans B)
    const int bhi  = ((lane >> 3) & 1) * 8;
    const int vrow = ((lane >> 3) & 1) * 8 + (lane & 7);  // V (trans B)
    const int vhi  = (lane >> 4) * 8;

    #pragma unroll 1
    for (int ph = 0; ph < 2; ph++) {
        const int qb = ph ? (15 - blockIdx.x) : blockIdx.x;
        const int q0 = qb * 128;
        const int nkb = 2 * qb + 2;

        __syncthreads();          // protect ring reuse across phases
        issue(0, 0);
        if (nkb > 1) issue(1, 64);

        // Q fragments (q already scaled by 1/8 and rotary in gemm_qkv)
        uint32_t qf[4][4];
        {
            const int r0 = q0 + warp * 16 + (lane >> 2);
            #pragma unroll
            for (int t = 0; t < 4; t++) {
                int c = t * 16 + (lane & 3) * 2;
                qf[t][0] = *(const uint32_t*)&Qg[(size_t)r0 * HD + c];
                qf[t][1] = *(const uint32_t*)&Qg[(size_t)(r0 + 8) * HD + c];
                qf[t][2] = *(const uint32_t*)&Qg[(size_t)r0 * HD + c + 8];
                qf[t][3] = *(const uint32_t*)&Qg[(size_t)(r0 + 8) * HD + c + 8];
            }
        }

        float o[8][4];
        #pragma unroll
        for (int nt = 0; nt < 8; nt++)
            #pragma unroll
            for (int j = 0; j < 4; j++) o[nt][j] = 0.f;
        float mi0 = -INFINITY, mi1 = -INFINITY, li0 = 0.f, li1 = 0.f;

        #pragma unroll 1
        for (int kb = 0; kb < nkb; kb++) {
            const int st = kb - (kb / 3) * 3;
            const int kbase = kb * 64;
            if (kb + 1 < nkb) cp_wait<1>(); else cp_wait<0>();
            __syncthreads();
            if (kb + 2 < nkb) issue((kb + 2) - ((kb + 2) / 3) * 3, kbase + 128);

            const __nv_bfloat16* Ks = stageK(st);
            const __nv_bfloat16* Vs = stageV(st);

            const bool active = (kbase <= q0 + warp * 16 + 15);
            if (active) {
                // S = Q K^T
                float s[8][4];
                #pragma unroll
                for (int nt = 0; nt < 8; nt++)
                    #pragma unroll
                    for (int j = 0; j < 4; j++) s[nt][j] = 0.f;
                #pragma unroll
                for (int ks = 0; ks < 4; ks++) {
                    #pragma unroll
                    for (int np = 0; np < 4; np++) {
                        uint32_t t0, t1, t2, t3;
                        ldsm4(t0, t1, t2, t3,
                              sptr(Ks + (np * 16 + brow) * 72 + ks * 16 + bhi));
                        mma16(s[np * 2], qf[ks], t0, t1);
                        mma16(s[np * 2 + 1], qf[ks], t2, t3);
                    }
                }

                // masks
                const int row0 = q0 + warp * 16 + (lane >> 2);
                const bool needc = (kbase + 63) > (q0 + warp * 16);
                #pragma unroll
                for (int nt = 0; nt < 8; nt++) {
                    int c = nt * 8 + (lane & 3) * 2;
                    unsigned char mb0 = maskp[kbase + c], mb1 = maskp[kbase + c + 1];
                    if (mb0) { s[nt][0] = -INFINITY; s[nt][2] = -INFINITY; }
                    if (mb1) { s[nt][1] = -INFINITY; s[nt][3] = -INFINITY; }
                    if (needc) {
                        int cg = kbase + c;
                        if (cg     > row0)     s[nt][0] = -INFINITY;
                        if (cg + 1 > row0)     s[nt][1] = -INFINITY;
                        if (cg     > row0 + 8) s[nt][2] = -INFINITY;
                        if (cg + 1 > row0 + 8) s[nt][3] = -INFINITY;
                    }
                }

                // online softmax
                float mx0 = -INFINITY, mx1 = -INFINITY;
                #pragma unroll
                for (int nt = 0; nt < 8; nt++) {
                    mx0 = fmaxf(mx0, fmaxf(s[nt][0], s[nt][1]));
                    mx1 = fmaxf(mx1, fmaxf(s[nt][2], s[nt][3]));
                }
                mx0 = fmaxf(mx0, __shfl_xor_sync(0xFFFFFFFFu, mx0, 1));
                mx0 = fmaxf(mx0, __shfl_xor_sync(0xFFFFFFFFu, mx0, 2));
                mx1 = fmaxf(mx1, __shfl_xor_sync(0xFFFFFFFFu, mx1, 1));
                mx1 = fmaxf(mx1, __shfl_xor_sync(0xFFFFFFFFu, mx1, 2));
                float mt0 = fmaxf(mi0, mx0), mt1 = fmaxf(mi1, mx1);
                float ms0 = (mt0 == -INFINITY) ? 0.f : mt0;
                float ms1 = (mt1 == -INFINITY) ? 0.f : mt1;
                float al0 = __expf(mi0 - ms0), al1 = __expf(mi1 - ms1);
                mi0 = mt0; mi1 = mt1;
                float rs0 = 0.f, rs1 = 0.f;
                #pragma unroll
                for (int nt = 0; nt < 8; nt++) {
                    s[nt][0] = __expf(s[nt][0] - ms0); rs0 += s[nt][0];
                    s[nt][1] = __expf(s[nt][1] - ms0); rs0 += s[nt][1];
                    s[nt][2] = __expf(s[nt][2] - ms1); rs1 += s[nt][2];
                    s[nt][3] = __expf(s[nt][3] - ms1); rs1 += s[nt][3];
                }
                rs0 += __shfl_xor_sync(0xFFFFFFFFu, rs0, 1);
                rs0 += __shfl_xor_sync(0xFFFFFFFFu, rs0, 2);
                rs1 += __shfl_xor_sync(0xFFFFFFFFu, rs1, 1);
                rs1 += __shfl_xor_sync(0xFFFFFFFFu, rs1, 2);
                li0 = li0 * al0 + rs0;
                li1 = li1 * al1 + rs1;
                #pragma unroll
                for (int nt = 0; nt < 8; nt++) {
                    o[nt][0] *= al0; o[nt][1] *= al0;
                    o[nt][2] *= al1; o[nt][3] *= al1;
                }

                // P accum -> bf16 A-fragments (register-local), O += P V
                #pragma unroll
                for (int t = 0; t < 4; t++) {
                    uint32_t pa[4];
                    pa[0] = pack_bf16(s[2 * t][0],     s[2 * t][1]);
                    pa[1] = pack_bf16(s[2 * t][2],     s[2 * t][3]);
                    pa[2] = pack_bf16(s[2 * t + 1][0], s[2 * t + 1][1]);
                    pa[3] = pack_bf16(s[2 * t + 1][2], s[2 * t + 1][3]);
                    #pragma unroll
                    for (int np = 0; np < 4; np++) {
                        uint32_t t0, t1, t2, t3;
                        ldsm4t(t0, t1, t2, t3,
                               sptr(Vs + (t * 16 + vrow) * 72 + np * 16 + vhi));
                        mma16(o[np * 2], pa, t0, t1);
                        mma16(o[np * 2 + 1], pa, t2, t3);
                    }
                }
            }
        }

        // epilogue: normalize + write ctx (bf16)
        const float inv0 = 1.f / li0, inv1 = 1.f / li1;
        const int r0 = q0 + warp * 16 + (lane >> 2);
        #pragma unroll
        for (int nt = 0; nt < 8; nt++) {
            int dc = nt * 8 + (lane & 3) * 2;
            uint32_t w0 = pack_bf16(o[nt][0] * inv0, o[nt][1] * inv0);
            uint32_t w1 = pack_bf16(o[nt][2] * inv1, o[nt][3] * inv1);
            *(uint32_t*)&g_ctx[(size_t)(batch * SEQ + r0) * D_MODEL + h * HD + dc] = w0;
            *(uint32_t*)&g_ctx[(size_t)(batch * SEQ + r0 + 8) * D_MODEL + h * HD + dc] = w1;
        }
    }
}

// ---------------------------------------------------------------------------
extern "C" void kernel_launch(void* const* d_in, const int* in_sizes, int n_in,
                              void* d_out, int out_size) {
    const float* x  = (const float*)d_in[0];
    const unsigned char* kpm = (const unsigned char*)d_in[1];
    const float* qw = (const float*)d_in[2];
    const float* kw = (const float*)d_in[3];
    const float* vw = (const float*)d_in[4];
    const float* ow = (const float*)d_in[5];
    const float* ob = (const float*)d_in[6];
    const float* lg = (const float*)d_in[7];
    const float* lb = (const float*)d_in[8];
    float* out = (float*)d_out;

    static bool attr_done = false;
    if (!attr_done) {
        cudaFuncSetAttribute(gemm_qkv, cudaFuncAttributeMaxDynamicSharedMemorySize, G_SMEM_BYTES);
        cudaFuncSetAttribute(gemm_out, cudaFuncAttributeMaxDynamicSharedMemorySize, G_SMEM_BYTES);
        cudaFuncSetAttribute(attn_kernel, cudaFuncAttributeMaxDynamicSharedMemorySize, A_SMEM_BYTES);
        attr_done = true;
    }

    emb_kernel<<<(SEQ * HD + 255) / 256, 256>>>();
    wcvt_kernel<<<dim3(D_MODEL * D_MODEL / (256 * 4), 4), 256>>>(qw, kw, vw, ow);
    ln_kernel<<<MTOT, 256>>>(x, lg, lb);
    gemm_qkv<<<dim3(24, 64), 256, G_SMEM_BYTES>>>();
    attn_kernel<<<dim3(8, 64), 256, A_SMEM_BYTES>>>(kpm);
    gemm_out<<<dim3(8, 64), 256, G_SMEM_BYTES>>>(ob, x, out);
}

// round 8
// speedup vs baseline: 5.8870x; 1.0452x over previous
#include <cuda_runtime.h>
#include <cuda_bf16.h>
#include <cstdint>
#include <math.h>

#define D_MODEL 1024
#define NHEAD   16
#define HD      64
#define SEQ     2048
#define BATCH   4
#define MTOT    (BATCH*SEQ)      // 8192
#define BHN     (BATCH*NHEAD)    // 64

static __device__ __nv_bfloat16 g_xln[MTOT * D_MODEL];
static __device__ __nv_bfloat16 g_q[BHN * SEQ * HD];
static __device__ __nv_bfloat16 g_k[BHN * SEQ * HD];
static __device__ __nv_bfloat16 g_v[BHN * SEQ * HD];
static __device__ __nv_bfloat16 g_ctx[MTOT * D_MODEL];
static __device__ __nv_bfloat16 g_wq[D_MODEL * D_MODEL];
static __device__ __nv_bfloat16 g_wk[D_MODEL * D_MODEL];
static __device__ __nv_bfloat16 g_wv[D_MODEL * D_MODEL];
static __device__ __nv_bfloat16 g_wo[D_MODEL * D_MODEL];
static __device__ float g_emb[SEQ * HD];

// GEMM smem: 3 stages x (A[128] + B[128]) rows of 72 bf16 (144B pitch)
#define G_PITCHB  144
#define G_ASIZE   (128 * G_PITCHB)          // 18432
#define G_STAGE_BYTES (2 * G_ASIZE)          // 36864
#define G_SMEM_BYTES  (3 * G_STAGE_BYTES)    // 110592
// attn smem: 3 stages x (K[64][72] + V[64][72]) bf16
#define A_STAGE_BYTES 18432
#define A_SMEM_BYTES  (3 * A_STAGE_BYTES)

// ---------------------------------------------------------------------------
// helpers
// ---------------------------------------------------------------------------
__device__ __forceinline__ uint32_t sptr(const void* p) {
    return (uint32_t)__cvta_generic_to_shared(p);
}
__device__ __forceinline__ uint32_t pack_bf16(float lo, float hi) {
    uint32_t d;
    asm("cvt.rn.bf16x2.f32 %0, %1, %2;" : "=r"(d) : "f"(hi), "f"(lo));
    return d;
}
__device__ __forceinline__ void ldsm4(uint32_t& r0, uint32_t& r1, uint32_t& r2, uint32_t& r3,
                                      uint32_t addr) {
    asm volatile("ldmatrix.sync.aligned.m8n8.x4.shared.b16 {%0,%1,%2,%3}, [%4];"
                 : "=r"(r0), "=r"(r1), "=r"(r2), "=r"(r3) : "r"(addr));
}
__device__ __forceinline__ void ldsm4t(uint32_t& r0, uint32_t& r1, uint32_t& r2, uint32_t& r3,
                                       uint32_t addr) {
    asm volatile("ldmatrix.sync.aligned.m8n8.x4.trans.shared.b16 {%0,%1,%2,%3}, [%4];"
                 : "=r"(r0), "=r"(r1), "=r"(r2), "=r"(r3) : "r"(addr));
}
__device__ __forceinline__ void mma16(float* c, const uint32_t* a, uint32_t b0, uint32_t b1) {
    asm volatile("mma.sync.aligned.m16n8k16.row.col.f32.bf16.bf16.f32 "
                 "{%0,%1,%2,%3}, {%4,%5,%6,%7}, {%8,%9}, {%0,%1,%2,%3};"
                 : "+f"(c[0]), "+f"(c[1]), "+f"(c[2]), "+f"(c[3])
                 : "r"(a[0]), "r"(a[1]), "r"(a[2]), "r"(a[3]), "r"(b0), "r"(b1));
}
__device__ __forceinline__ void cpa16(uint32_t dst, const void* src) {
    asm volatile("cp.async.cg.shared.global [%0], [%1], 16;" :: "r"(dst), "l"(src));
}
__device__ __forceinline__ void cp_commit() { asm volatile("cp.async.commit_group;"); }
template<int N> __device__ __forceinline__ void cp_wait() {
    asm volatile("cp.async.wait_group %0;" :: "n"(N));
}

// ---------------------------------------------------------------------------
__global__ void emb_kernel() {
    int idx = blockIdx.x * blockDim.x + threadIdx.x;
    if (idx >= SEQ * HD) return;
    int s = idx / HD, d = idx % HD;
    int i = d & 31;
    double invf = exp(-((double)(2 * i) / 64.0) * log(10000.0));
    double ang = (double)s * invf;
    g_emb[idx] = (float)((d < 32) ? sin(ang) : cos(ang));
}

// all 4 weight matrices fp32 -> bf16 in one launch: grid (1024, 4)
__global__ __launch_bounds__(256) void wcvt_kernel(const float* __restrict__ qw,
                                                   const float* __restrict__ kw,
                                                   const float* __restrict__ vw,
                                                   const float* __restrict__ ow) {
    const int which = blockIdx.y;
    const float* src = (which == 0) ? qw : (which == 1) ? kw : (which == 2) ? vw : ow;
    __nv_bfloat16* dst = (which == 0) ? g_wq : (which == 1) ? g_wk : (which == 2) ? g_wv : g_wo;
    int i = (blockIdx.x * 256 + threadIdx.x) * 4;
    float4 v = *(const float4*)(src + i);
    uint2 o;
    o.x = pack_bf16(v.x, v.y);
    o.y = pack_bf16(v.z, v.w);
    *(uint2*)(dst + i) = o;
}

// ---------------------------------------------------------------------------
__global__ __launch_bounds__(256) void ln_kernel(const float* __restrict__ x,
                                                 const float* __restrict__ gam,
                                                 const float* __restrict__ bet) {
    int row = blockIdx.x;
    const float4* xr = (const float4*)(x + (size_t)row * D_MODEL);
    float4 v = xr[threadIdx.x];
    float sum = v.x + v.y + v.z + v.w;
    float sq  = v.x*v.x + v.y*v.y + v.z*v.z + v.w*v.w;
    #pragma unroll
    for (int o = 16; o; o >>= 1) {
        sum += __shfl_xor_sync(0xFFFFFFFFu, sum, o);
        sq  += __shfl_xor_sync(0xFFFFFFFFu, sq, o);
    }
    __shared__ float ssum[8], ssq[8];
    int w = threadIdx.x >> 5, l = threadIdx.x & 31;
    if (!l) { ssum[w] = sum; ssq[w] = sq; }
    __syncthreads();
    if (w == 0) {
        sum = (l < 8) ? ssum[l] : 0.f;
        sq  = (l < 8) ? ssq[l]  : 0.f;
        #pragma unroll
        for (int o = 4; o; o >>= 1) {
            sum += __shfl_xor_sync(0xFFFFFFFFu, sum, o);
            sq  += __shfl_xor_sync(0xFFFFFFFFu, sq, o);
        }
        if (!l) { ssum[0] = sum; ssq[0] = sq; }
    }
    __syncthreads();
    float mu  = ssum[0] * (1.f / D_MODEL);
    float var = ssq[0] * (1.f / D_MODEL) - mu * mu;
    float rs  = rsqrtf(var + 1e-5f);
    int c = threadIdx.x * 4;
    float4 g4 = *(const float4*)(gam + c);
    float4 b4 = *(const float4*)(bet + c);
    uint2 o;
    o.x = pack_bf16((v.x - mu) * rs * g4.x + b4.x, (v.y - mu) * rs * g4.y + b4.y);
    o.y = pack_bf16((v.z - mu) * rs * g4.z + b4.z, (v.w - mu) * rs * g4.w + b4.w);
    *(uint2*)(g_xln + (size_t)row * D_MODEL + c) = o;
}

// ---------------------------------------------------------------------------
// bf16 GEMM core: CTA 128x128, k-stage 64 (16 iters), 3-stage cp.async ring,
// ONE __syncthreads per k-iteration. 8 warps (2m x 4n), mma m16n8k16.
// ---------------------------------------------------------------------------
struct GemmAcc { float a[4][4][4]; };

__device__ __forceinline__ void gemm_core(const __nv_bfloat16* __restrict__ A,
                                          const __nv_bfloat16* __restrict__ B,
                                          int m0, int n0, GemmAcc& G, char* sm) {
    const int tid  = threadIdx.x;
    const int lane = tid & 31, warp = tid >> 5;
    const int wm = warp >> 2, wn = warp & 3;

    #pragma unroll
    for (int mt = 0; mt < 4; mt++)
        #pragma unroll
        for (int nt = 0; nt < 4; nt++)
            #pragma unroll
            for (int j = 0; j < 4; j++) G.a[mt][nt][j] = 0.f;

    auto issue = [&](int st, int k0) {
        char* As = sm + st * G_STAGE_BYTES;
        char* Bs = As + G_ASIZE;
        #pragma unroll
        for (int t = 0; t < 4; t++) {
            int idx = tid + t * 256;           // 0..1023
            int row = idx >> 3;                // 128 rows
            int cb  = (idx & 7) * 16;          // 8 x 16B per 128B row
            cpa16(sptr(As + row * G_PITCHB + cb),
                  (const char*)(A + (size_t)(m0 + row) * D_MODEL + k0) + cb);
            cpa16(sptr(Bs + row * G_PITCHB + cb),
                  (const char*)(B + (size_t)(n0 + row) * D_MODEL + k0) + cb);
        }
        cp_commit();
    };

    issue(0, 0);
    issue(1, 64);

    // ldmatrix lane addressing (byte offsets, pitch 144B)
    const int arow = (lane & 15);
    const int ahi  = (lane >> 4) * 16;               // bytes
    const int brow = ((lane >> 4) & 1) * 8 + (lane & 7);
    const int bhi  = ((lane >> 3) & 1) * 16;         // bytes

    for (int kt = 0; kt < 16; kt++) {
        const int st = kt - (kt / 3) * 3;
        if (kt < 15) cp_wait<1>(); else cp_wait<0>();
        __syncthreads();
        if (kt + 2 < 16) issue((kt + 2) - ((kt + 2) / 3) * 3, (kt + 2) * 64);

        char* As = sm + st * G_STAGE_BYTES;
        char* Bs = As + G_ASIZE;
        #pragma unroll
        for (int ks = 0; ks < 4; ks++) {
            const int kkB = ks * 32;      // 16 bf16 = 32 bytes per slice
            uint32_t af[4][4];
            #pragma unroll
            for (int mt = 0; mt < 4; mt++)
                ldsm4(af[mt][0], af[mt][1], af[mt][2], af[mt][3],
                      sptr(As + (wm * 64 + mt * 16 + arow) * G_PITCHB + kkB + ahi));
            uint32_t bf[4][2];
            #pragma unroll
            for (int np = 0; np < 2; np++) {
                uint32_t t0, t1, t2, t3;
                ldsm4(t0, t1, t2, t3,
                      sptr(Bs + (wn * 32 + np * 16 + brow) * G_PITCHB + kkB + bhi));
                bf[np * 2][0] = t0;     bf[np * 2][1] = t1;
                bf[np * 2 + 1][0] = t2; bf[np * 2 + 1][1] = t3;
            }
            #pragma unroll
            for (int mt = 0; mt < 4; mt++)
                #pragma unroll
                for (int nt = 0; nt < 4; nt++)
                    mma16(G.a[mt][nt], af[mt], bf[nt][0], bf[nt][1]);
        }
    }
}

// ---------------------------------------------------------------------------
// QKV proj: grid (24, 64). Fused rotary (+0.125 scale on q) + head-split.
// ---------------------------------------------------------------------------
__global__ __launch_bounds__(256, 2) void gemm_qkv() {
    extern __shared__ char dynsm_g[];
    const int m0 = blockIdx.y * 128;
    const int which = blockIdx.x >> 3;
    const int n0 = (blockIdx.x & 7) * 128;
    const __nv_bfloat16* W = (which == 0) ? g_wq : (which == 1) ? g_wk : g_wv;

    GemmAcc G;
    gemm_core(g_xln, W, m0, n0, G, dynsm_g);

    const int lane = threadIdx.x & 31, warp = threadIdx.x >> 5;
    const int wm = warp >> 2, wn = warp & 3;
    __nv_bfloat16* dst = (which == 0) ? g_q : (which == 1) ? g_k : g_v;

    #pragma unroll
    for (int mt = 0; mt < 4; mt++) {
        #pragma unroll
        for (int rh = 0; rh < 2; rh++) {
            int m = m0 + wm * 64 + mt * 16 + rh * 8 + (lane >> 2);
            int b = m >> 11, s = m & 2047;
            #pragma unroll
            for (int nt = 0; nt < 4; nt++) {
                int n  = n0 + wn * 32 + nt * 8 + (lane & 3) * 2;
                int h  = n >> 6, dc = n & 63;
                float ex = 1.f, ey = 1.f;
                if (which < 2) {
                    float2 e = *(const float2*)&g_emb[s * HD + dc];
                    ex = e.x; ey = e.y;
                    if (which == 0) { ex *= 0.125f; ey *= 0.125f; }
                }
                uint32_t o = pack_bf16(G.a[mt][nt][rh * 2 + 0] * ex,
                                       G.a[mt][nt][rh * 2 + 1] * ey);
                *(uint32_t*)&dst[((size_t)(b * NHEAD + h) * SEQ + s) * HD + dc] = o;
            }
        }
    }
}

// ---------------------------------------------------------------------------
// out proj + bias + residual: grid (8, 64)
// ---------------------------------------------------------------------------
__global__ __launch_bounds__(256, 2) void gemm_out(const float* __restrict__ ob,
                                                   const float* __restrict__ x,
                                                   float* __restrict__ out) {
    extern __shared__ char dynsm_o[];
    const int m0 = blockIdx.y * 128;
    const int n0 = blockIdx.x * 128;

    GemmAcc G;
    gemm_core(g_ctx, g_wo, m0, n0, G, dynsm_o);

    const int lane = threadIdx.x & 31, warp = threadIdx.x >> 5;
    const int wm = warp >> 2, wn = warp & 3;

    #pragma unroll
    for (int mt = 0; mt < 4; mt++) {
        #pragma unroll
        for (int rh = 0; rh < 2; rh++) {
            int m = m0 + wm * 64 + mt * 16 + rh * 8 + (lane >> 2);
            #pragma unroll
            for (int nt = 0; nt < 4; nt++) {
                int n = n0 + wn * 32 + nt * 8 + (lane & 3) * 2;
                float2 bb = *(const float2*)&ob[n];
                float2 xx = *(const float2*)&x[(size_t)m * D_MODEL + n];
                float2 o;
                o.x = G.a[mt][nt][rh * 2 + 0] + bb.x + xx.x;
                o.y = G.a[mt][nt][rh * 2 + 1] + bb.y + xx.y;
                *(float2*)&out[(size_t)m * D_MODEL + n] = o;
            }
        }
    }
}

// ---------------------------------------------------------------------------
// Flash attention, bf16 mma. grid (8, 64). Two q-tiles per CTA
// (qb = bx and 15-bx). 3-stage K/V ring, one __syncthreads per k-block.
// ---------------------------------------------------------------------------
__global__ __launch_bounds__(256, 2) void attn_kernel(const unsigned char* __restrict__ kpm) {
    extern __shared__ char dynsm_a[];

    const int tid = threadIdx.x, lane = tid & 31, warp = tid >> 5;
    const int bh = blockIdx.y;
    const int batch = bh >> 4, h = bh & 15;

    const __nv_bfloat16* __restrict__ Qg = g_q + (size_t)bh * SEQ * HD;
    const __nv_bfloat16* __restrict__ Kg = g_k + (size_t)bh * SEQ * HD;
    const __nv_bfloat16* __restrict__ Vg = g_v + (size_t)bh * SEQ * HD;
    const unsigned char* __restrict__ maskp = kpm + (size_t)batch * SEQ;

    const int ch0 = tid, ch1 = tid + 256;
    const int lr0 = ch0 >> 3, lc0 = (ch0 & 7) * 8;
    const int lr1 = ch1 >> 3, lc1 = (ch1 & 7) * 8;

    auto stageK = [&](int st) { return (__nv_bfloat16*)(dynsm_a + st * A_STAGE_BYTES); };
    auto stageV = [&](int st) { return (__nv_bfloat16*)(dynsm_a + st * A_STAGE_BYTES + 9216); };

    auto issue = [&](int st, int kbase) {
        __nv_bfloat16* Ks = stageK(st);
        __nv_bfloat16* Vs = stageV(st);
        cpa16(sptr(Ks + lr0 * 72 + lc0), Kg + (size_t)(kbase + lr0) * HD + lc0);
        cpa16(sptr(Ks + lr1 * 72 + lc1), Kg + (size_t)(kbase + lr1) * HD + lc1);
        cpa16(sptr(Vs + lr0 * 72 + lc0), Vg + (size_t)(kbase + lr0) * HD + lc0);
        cpa16(sptr(Vs + lr1 * 72 + lc1), Vg + (size_t)(kbase + lr1) * HD + lc1);
        cp_commit();
    };

    const int brow = ((lane >> 4) & 1) * 8 + (lane & 7);  // K (non-trans B)
    const int bhi  = ((lane >> 3) & 1) * 8;
    const int vrow = ((lane >> 3) & 1) * 8 + (lane & 7);  // V (trans B)
    const int vhi  = (lane >> 4) * 8;

    #pragma unroll 1
    for (int ph = 0; ph < 2; ph++) {
        const int qb = ph ? (15 - blockIdx.x) : blockIdx.x;
        const int q0 = qb * 128;
        const int nkb = 2 * qb + 2;

        __syncthreads();          // protect ring reuse across phases
        issue(0, 0);
        if (nkb > 1) issue(1, 64);

        uint32_t qf[4][4];
        {
            const int r0 = q0 + warp * 16 + (lane >> 2);
            #pragma unroll
            for (int t = 0; t < 4; t++) {
                int c = t * 16 + (lane & 3) * 2;
                qf[t][0] = *(const uint32_t*)&Qg[(size_t)r0 * HD + c];
                qf[t][1] = *(const uint32_t*)&Qg[(size_t)(r0 + 8) * HD + c];
                qf[t][2] = *(const uint32_t*)&Qg[(size_t)r0 * HD + c + 8];
                qf[t][3] = *(const uint32_t*)&Qg[(size_t)(r0 + 8) * HD + c + 8];
            }
        }

        float o[8][4];
        #pragma unroll
        for (int nt = 0; nt < 8; nt++)
            #pragma unroll
            for (int j = 0; j < 4; j++) o[nt][j] = 0.f;
        float mi0 = -INFINITY, mi1 = -INFINITY, li0 = 0.f, li1 = 0.f;

        #pragma unroll 1
        for (int kb = 0; kb < nkb; kb++) {
            const int st = kb - (kb / 3) * 3;
            const int kbase = kb * 64;
            if (kb + 1 < nkb) cp_wait<1>(); else cp_wait<0>();
            __syncthreads();
            if (kb + 2 < nkb) issue((kb + 2) - ((kb + 2) / 3) * 3, kbase + 128);

            const __nv_bfloat16* Ks = stageK(st);
            const __nv_bfloat16* Vs = stageV(st);

            const bool active = (kbase <= q0 + warp * 16 + 15);
            if (active) {
                float s[8][4];
                #pragma unroll
                for (int nt = 0; nt < 8; nt++)
                    #pragma unroll
                    for (int j = 0; j < 4; j++) s[nt][j] = 0.f;
                #pragma unroll
                for (int ks = 0; ks < 4; ks++) {
                    #pragma unroll
                    for (int np = 0; np < 4; np++) {
                        uint32_t t0, t1, t2, t3;
                        ldsm4(t0, t1, t2, t3,
                              sptr(Ks + (np * 16 + brow) * 72 + ks * 16 + bhi));
                        mma16(s[np * 2], qf[ks], t0, t1);
                        mma16(s[np * 2 + 1], qf[ks], t2, t3);
                    }
                }

                const int row0 = q0 + warp * 16 + (lane >> 2);
                const bool needc = (kbase + 63) > (q0 + warp * 16);
                #pragma unroll
                for (int nt = 0; nt < 8; nt++) {
                    int c = nt * 8 + (lane & 3) * 2;
                    unsigned char mb0 = maskp[kbase + c], mb1 = maskp[kbase + c + 1];
                    if (mb0) { s[nt][0] = -INFINITY; s[nt][2] = -INFINITY; }
                    if (mb1) { s[nt][1] = -INFINITY; s[nt][3] = -INFINITY; }
                    if (needc) {
                        int cg = kbase + c;
                        if (cg     > row0)     s[nt][0] = -INFINITY;
                        if (cg + 1 > row0)     s[nt][1] = -INFINITY;
                        if (cg     > row0 + 8) s[nt][2] = -INFINITY;
                        if (cg + 1 > row0 + 8) s[nt][3] = -INFINITY;
                    }
                }

                float mx0 = -INFINITY, mx1 = -INFINITY;
                #pragma unroll
                for (int nt = 0; nt < 8; nt++) {
                    mx0 = fmaxf(mx0, fmaxf(s[nt][0], s[nt][1]));
                    mx1 = fmaxf(mx1, fmaxf(s[nt][2], s[nt][3]));
                }
                mx0 = fmaxf(mx0, __shfl_xor_sync(0xFFFFFFFFu, mx0, 1));
                mx0 = fmaxf(mx0, __shfl_xor_sync(0xFFFFFFFFu, mx0, 2));
                mx1 = fmaxf(mx1, __shfl_xor_sync(0xFFFFFFFFu, mx1, 1));
                mx1 = fmaxf(mx1, __shfl_xor_sync(0xFFFFFFFFu, mx1, 2));
                float mt0 = fmaxf(mi0, mx0), mt1 = fmaxf(mi1, mx1);
                float ms0 = (mt0 == -INFINITY) ? 0.f : mt0;
                float ms1 = (mt1 == -INFINITY) ? 0.f : mt1;
                float al0 = __expf(mi0 - ms0), al1 = __expf(mi1 - ms1);
                mi0 = mt0; mi1 = mt1;
                float rs0 = 0.f, rs1 = 0.f;
                #pragma unroll
                for (int nt = 0; nt < 8; nt++) {
                    s[nt][0] = __expf(s[nt][0] - ms0); rs0 += s[nt][0];
                    s[nt][1] = __expf(s[nt][1] - ms0); rs0 += s[nt][1];
                    s[nt][2] = __expf(s[nt][2] - ms1); rs1 += s[nt][2];
                    s[nt][3] = __expf(s[nt][3] - ms1); rs1 += s[nt][3];
                }
                rs0 += __shfl_xor_sync(0xFFFFFFFFu, rs0, 1);
                rs0 += __shfl_xor_sync(0xFFFFFFFFu, rs0, 2);
                rs1 += __shfl_xor_sync(0xFFFFFFFFu, rs1, 1);
                rs1 += __shfl_xor_sync(0xFFFFFFFFu, rs1, 2);
                li0 = li0 * al0 + rs0;
                li1 = li1 * al1 + rs1;
                #pragma unroll
                for (int nt = 0; nt < 8; nt++) {
                    o[nt][0] *= al0; o[nt][1] *= al0;
                    o[nt][2] *= al1; o[nt][3] *= al1;
                }

                #pragma unroll
                for (int t = 0; t < 4; t++) {
                    uint32_t pa[4];
                    pa[0] = pack_bf16(s[2 * t][0],     s[2 * t][1]);
                    pa[1] = pack_bf16(s[2 * t][2],     s[2 * t][3]);
                    pa[2] = pack_bf16(s[2 * t + 1][0], s[2 * t + 1][1]);
                    pa[3] = pack_bf16(s[2 * t + 1][2], s[2 * t + 1][3]);
                    #pragma unroll
                    for (int np = 0; np < 4; np++) {
                        uint32_t t0, t1, t2, t3;
                        ldsm4t(t0, t1, t2, t3,
                               sptr(Vs + (t * 16 + vrow) * 72 + np * 16 + vhi));
                        mma16(o[np * 2], pa, t0, t1);
                        mma16(o[np * 2 + 1], pa, t2, t3);
                    }
                }
            }
        }

        const float inv0 = 1.f / li0, inv1 = 1.f / li1;
        const int r0 = q0 + warp * 16 + (lane >> 2);
        #pragma unroll
        for (int nt = 0; nt < 8; nt++) {
            int dc = nt * 8 + (lane & 3) * 2;
            uint32_t w0 = pack_bf16(o[nt][0] * inv0, o[nt][1] * inv0);
            uint32_t w1 = pack_bf16(o[nt][2] * inv1, o[nt][3] * inv1);
            *(uint32_t*)&g_ctx[(size_t)(batch * SEQ + r0) * D_MODEL + h * HD + dc] = w0;
            *(uint32_t*)&g_ctx[(size_t)(batch * SEQ + r0 + 8) * D_MODEL + h * HD + dc] = w1;
        }
    }
}

// ---------------------------------------------------------------------------
extern "C" void kernel_launch(void* const* d_in, const int* in_sizes, int n_in,
                              void* d_out, int out_size) {
    const float* x  = (const float*)d_in[0];
    const unsigned char* kpm = (const unsigned char*)d_in[1];
    const float* qw = (const float*)d_in[2];
    const float* kw = (const float*)d_in[3];
    const float* vw = (const float*)d_in[4];
    const float* ow = (const float*)d_in[5];
    const float* ob = (const float*)d_in[6];
    const float* lg = (const float*)d_in[7];
    const float* lb = (const float*)d_in[8];
    float* out = (float*)d_out;

    static bool attr_done = false;
    if (!attr_done) {
        cudaFuncSetAttribute(gemm_qkv, cudaFuncAttributeMaxDynamicSharedMemorySize, G_SMEM_BYTES);
        cudaFuncSetAttribute(gemm_out, cudaFuncAttributeMaxDynamicSharedMemorySize, G_SMEM_BYTES);
        cudaFuncSetAttribute(attn_kernel, cudaFuncAttributeMaxDynamicSharedMemorySize, A_SMEM_BYTES);
        attr_done = true;
    }

    emb_kernel<<<(SEQ * HD + 255) / 256, 256>>>();
    wcvt_kernel<<<dim3(D_MODEL * D_MODEL / (256 * 4), 4), 256>>>(qw, kw, vw, ow);
    ln_kernel<<<MTOT, 256>>>(x, lg, lb);
    gemm_qkv<<<dim3(24, 64), 256, G_SMEM_BYTES>>>();
    attn_kernel<<<dim3(8, 64), 256, A_SMEM_BYTES>>>(kpm);
    gemm_out<<<dim3(8, 64), 256, G_SMEM_BYTES>>>(ob, x, out);
}